// round 8
// baseline (speedup 1.0000x reference)
#include <cuda_runtime.h>
#include <cuda_bf16.h>
#include <math.h>
#include <stdint.h>

#define M_DIM 1024
#define N_DIM 4096
#define D_DIM 128
#define H_DIM 32
#define P_POS 2048
#define L_DIM 4096

// --- arch-specific feature gate (tcgen05 only legal in sm_103a-specific pass)
#if defined(__CUDA_ARCH__)
#if defined(__CUDA_ARCH_FEAT_SM103_ALL)
#define HAS_TC 1
#elif defined(__CUDA_ARCH_SPECIFIC__) && (__CUDA_ARCH_SPECIFIC__ == 1030)
#define HAS_TC 1
#endif
#endif
#ifndef HAS_TC
#define HAS_TC 0
#endif

// bf16-split operands.
__device__ __nv_bfloat16 g_Xhi[M_DIM * (size_t)N_DIM];
__device__ __nv_bfloat16 g_Xlo[M_DIM * (size_t)N_DIM];
__device__ __nv_bfloat16 g_Whi[3 * (size_t)N_DIM * N_DIM];
__device__ __nv_bfloat16 g_Wlo[3 * (size_t)N_DIM * N_DIM];
// Q projection output, bf16 hi/lo, [M][N] row-major.
__device__ __nv_bfloat16 g_Qhi[M_DIM * (size_t)N_DIM];
__device__ __nv_bfloat16 g_Qlo[M_DIM * (size_t)N_DIM];
// Merged cache: K_all [H][L][D], V_all transposed [H][D][L].
// Fresh region [P, P+M) written directly by the GEMM epilogue.
__device__ __nv_bfloat16 g_KAhi[(size_t)H_DIM * L_DIM * D_DIM];
__device__ __nv_bfloat16 g_KAlo[(size_t)H_DIM * L_DIM * D_DIM];
__device__ __nv_bfloat16 g_VThi[(size_t)H_DIM * D_DIM * L_DIM];
__device__ __nv_bfloat16 g_VTlo[(size_t)H_DIM * D_DIM * L_DIM];

// ---------------------------------------------------------------------------
// helpers
// ---------------------------------------------------------------------------
__device__ __forceinline__ uint32_t smem_u32(const void* p) {
    return (uint32_t)__cvta_generic_to_shared(p);
}
__device__ __forceinline__ void cp16s(uint32_t s, const void* g) {
    asm volatile("cp.async.cg.shared.global [%0], [%1], 16;" :: "r"(s), "l"(g));
}
#define CP_COMMIT asm volatile("cp.async.commit_group;")

__device__ __forceinline__ uint32_t split2(float a, float b, uint32_t& lo) {
    __nv_bfloat16 ah = __float2bfloat16_rn(a);
    __nv_bfloat16 bh = __float2bfloat16_rn(b);
    __nv_bfloat16 al = __float2bfloat16_rn(a - __bfloat162float(ah));
    __nv_bfloat16 bl = __float2bfloat16_rn(b - __bfloat162float(bh));
    lo = (uint32_t)__bfloat16_as_ushort(al) | ((uint32_t)__bfloat16_as_ushort(bl) << 16);
    return (uint32_t)__bfloat16_as_ushort(ah) | ((uint32_t)__bfloat16_as_ushort(bh) << 16);
}

#define SWZ(x) ((x) ^ ((((uint32_t)(x)) >> 3) & 0x70))

#if HAS_TC
__device__ __forceinline__ uint32_t elect1() {
    uint32_t p;
    asm volatile("{\n\t.reg .pred p;\n\telect.sync _|p, 0xFFFFFFFF;\n\t"
                 "selp.b32 %0, 1, 0, p;\n\t}" : "=r"(p));
    return p;
}
__device__ __forceinline__ void mbar_init(uint32_t m, uint32_t cnt) {
    asm volatile("mbarrier.init.shared.b64 [%0], %1;" :: "r"(m), "r"(cnt) : "memory");
}
__device__ __forceinline__ void mbar_wait(uint32_t m, uint32_t parity) {
    uint32_t done;
    asm volatile(
        "{\n\t.reg .pred p;\n\t"
        "mbarrier.try_wait.parity.acquire.cta.shared::cta.b64 p, [%1], %2;\n\t"
        "selp.b32 %0, 1, 0, p;\n\t}"
        : "=r"(done) : "r"(m), "r"(parity) : "memory");
    if (!done) {
        asm volatile(
            "{\n\t.reg .pred P1;\n\t"
            "WL_%=:\n\t"
            "mbarrier.try_wait.parity.acquire.cta.shared::cta.b64 P1, [%0], %1, 0x989680;\n\t"
            "@P1 bra.uni WD_%=;\n\t"
            "bra.uni WL_%=;\n\t"
            "WD_%=:\n\t}"
            :: "r"(m), "r"(parity) : "memory");
    }
}
__device__ __forceinline__ uint64_t mk_desc(uint32_t addr) {
    const uint64_t base = (uint64_t(2) << 61) | (uint64_t(1) << 46) |
                          (uint64_t(64) << 32) | (uint64_t(1) << 16);
    return base | ((uint64_t)(addr >> 4) & 0x3FFF);
}
__device__ __forceinline__ void mma_ss(uint32_t d, uint64_t ad, uint64_t bd,
                                       uint32_t idesc, uint32_t en) {
    asm volatile(
        "{\n\t.reg .pred p;\n\t"
        "setp.ne.u32 p, %4, 0;\n\t"
        "tcgen05.mma.cta_group::1.kind::f16 [%0], %1, %2, %3, {%5,%5,%5,%5}, p;\n\t}"
        :: "r"(d), "l"(ad), "l"(bd), "r"(idesc), "r"(en), "r"(0u) : "memory");
}
__device__ __forceinline__ void mma_ss_cg2(uint32_t d, uint64_t ad, uint64_t bd,
                                           uint32_t idesc, uint32_t en) {
    asm volatile(
        "{\n\t.reg .pred p;\n\t"
        "setp.ne.u32 p, %4, 0;\n\t"
        "tcgen05.mma.cta_group::2.kind::f16 [%0], %1, %2, %3, "
        "{%5,%5,%5,%5,%5,%5,%5,%5}, p;\n\t}"
        :: "r"(d), "l"(ad), "l"(bd), "r"(idesc), "r"(en), "r"(0u) : "memory");
}
__device__ __forceinline__ void mma_ts(uint32_t d, uint32_t at, uint64_t bd,
                                       uint32_t idesc, uint32_t en) {
    asm volatile(
        "{\n\t.reg .pred p;\n\t"
        "setp.ne.u32 p, %4, 0;\n\t"
        "tcgen05.mma.cta_group::1.kind::f16 [%0], [%1], %2, %3, {%5,%5,%5,%5}, p;\n\t}"
        :: "r"(d), "r"(at), "l"(bd), "r"(idesc), "r"(en), "r"(0u) : "memory");
}
#define LDTM32(r, a)                                                            \
    asm volatile(                                                               \
        "tcgen05.ld.sync.aligned.32x32b.x32.b32 "                               \
        "{%0,%1,%2,%3,%4,%5,%6,%7,%8,%9,%10,%11,%12,%13,%14,%15,"               \
        "%16,%17,%18,%19,%20,%21,%22,%23,%24,%25,%26,%27,%28,%29,%30,%31},[%32];" \
        : "=r"((r)[0]), "=r"((r)[1]), "=r"((r)[2]), "=r"((r)[3]),               \
          "=r"((r)[4]), "=r"((r)[5]), "=r"((r)[6]), "=r"((r)[7]),               \
          "=r"((r)[8]), "=r"((r)[9]), "=r"((r)[10]), "=r"((r)[11]),             \
          "=r"((r)[12]), "=r"((r)[13]), "=r"((r)[14]), "=r"((r)[15]),           \
          "=r"((r)[16]), "=r"((r)[17]), "=r"((r)[18]), "=r"((r)[19]),           \
          "=r"((r)[20]), "=r"((r)[21]), "=r"((r)[22]), "=r"((r)[23]),           \
          "=r"((r)[24]), "=r"((r)[25]), "=r"((r)[26]), "=r"((r)[27]),           \
          "=r"((r)[28]), "=r"((r)[29]), "=r"((r)[30]), "=r"((r)[31])            \
        : "r"(a))
#define STTM16(a, r)                                                            \
    asm volatile(                                                               \
        "tcgen05.st.sync.aligned.32x32b.x16.b32 [%0], "                         \
        "{%1,%2,%3,%4,%5,%6,%7,%8,%9,%10,%11,%12,%13,%14,%15,%16};"             \
        :: "r"(a),                                                              \
           "r"((r)[0]), "r"((r)[1]), "r"((r)[2]), "r"((r)[3]),                  \
           "r"((r)[4]), "r"((r)[5]), "r"((r)[6]), "r"((r)[7]),                  \
           "r"((r)[8]), "r"((r)[9]), "r"((r)[10]), "r"((r)[11]),                \
           "r"((r)[12]), "r"((r)[13]), "r"((r)[14]), "r"((r)[15])               \
        : "memory")
#define CLUSTER_BAR() do {                                                      \
    asm volatile("barrier.cluster.arrive.aligned;" ::: "memory");               \
    asm volatile("barrier.cluster.wait.aligned;" ::: "memory");                 \
} while (0)

// 128x128 bf16 tile (atom-blocked K-major SW128, 256B logical rows)
__device__ __forceinline__ void ld_tile(uint32_t sdst, const __nv_bfloat16* g,
                                        size_t stride, int tid) {
#pragma unroll
    for (int j = 0; j < 8; j++) {
        int u = tid + j * 256;
        int r = u >> 4;
        int c8 = u & 15;
        uint32_t so = (uint32_t)(((r >> 3) + (c8 >> 3) * 16) * 1024 +
                                 (r & 7) * 128 + (c8 & 7) * 16);
        cp16s(sdst + SWZ(so), g + (size_t)r * stride + c8 * 8);
    }
}
// 64x128 bf16 tile (atom-blocked, 8 atoms per 128B-col-block)
__device__ __forceinline__ void ld_tile_k64(uint32_t sdst, const __nv_bfloat16* g,
                                            size_t stride, int tid) {
#pragma unroll
    for (int j = 0; j < 4; j++) {
        int u = tid + j * 256;
        int r = u >> 4;
        int c8 = u & 15;
        uint32_t so = (uint32_t)(((r >> 3) + (c8 >> 3) * 8) * 1024 +
                                 (r & 7) * 128 + (c8 & 7) * 16);
        cp16s(sdst + SWZ(so), g + (size_t)r * stride + c8 * 8);
    }
}
// 128x64 bf16 tile (128B rows, single atom column)
__device__ __forceinline__ void ld_tile_v64(uint32_t sdst, const __nv_bfloat16* g,
                                            size_t stride, int tid) {
#pragma unroll
    for (int j = 0; j < 4; j++) {
        int u = tid + j * 256;
        int r = u >> 3;
        int c8 = u & 7;
        uint32_t so = (uint32_t)((r >> 3) * 1024 + (r & 7) * 128 + c8 * 16);
        cp16s(sdst + SWZ(so), g + (size_t)r * stride + c8 * 8);
    }
}
// 128 rows x 64 k bf16 (128B rows, 16 stacked atoms) — GEMM operand tile
__device__ __forceinline__ void ld_t128x64(uint32_t sdst, const __nv_bfloat16* g,
                                           int tid) {
#pragma unroll
    for (int j = 0; j < 4; j++) {
        int u = tid + j * 256;
        int r = u >> 3;
        int c8 = u & 7;
        uint32_t so = SWZ((uint32_t)(r * 128 + c8 * 16));
        cp16s(sdst + so, g + (size_t)r * N_DIM + c8 * 8);
    }
}
#endif  // HAS_TC

// ---------------------------------------------------------------------------
// Pre-pass: X fp32 -> bf16 hi/lo
// ---------------------------------------------------------------------------
__global__ __launch_bounds__(256) void convert_x_kernel(const float* __restrict__ X) {
    size_t i0 = ((size_t)blockIdx.x * 256 + threadIdx.x) * 8;
    float4 f0 = *(const float4*)&X[i0];
    float4 f1 = *(const float4*)&X[i0 + 4];
    uint4 hi, lo;
    hi.x = split2(f0.x, f0.y, lo.x);
    hi.y = split2(f0.z, f0.w, lo.y);
    hi.z = split2(f1.x, f1.y, lo.z);
    hi.w = split2(f1.z, f1.w, lo.w);
    *(uint4*)&g_Xhi[i0] = hi;
    *(uint4*)&g_Xlo[i0] = lo;
}

// ---------------------------------------------------------------------------
// Pre-pass: W [k][n] fp32 -> WT [n][k] bf16 hi/lo
// ---------------------------------------------------------------------------
__global__ __launch_bounds__(256) void convert_w_kernel(
    const float* __restrict__ Wq, const float* __restrict__ Wk,
    const float* __restrict__ Wv)
{
    __shared__ float sm[64][65];
    const float* W = (blockIdx.z == 0) ? Wq : (blockIdx.z == 1) ? Wk : Wv;
    const size_t wo = (size_t)blockIdx.z * N_DIM * N_DIM;
    const int k0 = blockIdx.x * 64;
    const int n0 = blockIdx.y * 64;
    const int tid = threadIdx.x;

#pragma unroll
    for (int j = 0; j < 16; j++) {
        int idx = tid + j * 256;
        int kr = idx >> 6, nc = idx & 63;
        sm[kr][nc] = W[(size_t)(k0 + kr) * N_DIM + n0 + nc];
    }
    __syncthreads();
#pragma unroll
    for (int j = 0; j < 8; j++) {
        int idx = tid + j * 256;
        int ni = idx >> 5, kp = idx & 31;
        float a = sm[kp * 2][ni];
        float b = sm[kp * 2 + 1][ni];
        uint32_t lo, hi = split2(a, b, lo);
        size_t o = wo + (size_t)(n0 + ni) * N_DIM + k0 + kp * 2;
        *(uint32_t*)&g_Whi[o] = hi;
        *(uint32_t*)&g_Wlo[o] = lo;
    }
}

// ---------------------------------------------------------------------------
// cg2 tcgen05 bf16x3-split GEMM. Pair tile M=256 x N=256, K-chunk 64.
// Each CTA loads its 128 A-rows + its 128 B-cols; rank0 issues cg2 MMA;
// commit multicasts completion to both CTAs.
// Epilogue: z=0 -> g_Q row-major; z=1 -> g_KA fresh rows; z=2 -> g_VT direct.
// ---------------------------------------------------------------------------
#define G2_TILE 16384
#define G2_BUFSZ (4 * G2_TILE)          // Ahi, Alo, Bhi, Blo
#define TC2_SMEM (2048 + 2 * G2_BUFSZ)  // 133120 B
#define G2_IDESC 0x10400490u            // f32 acc, bf16 a/b, N=256, M=256
#define G2_NCH 64

#if HAS_TC
__device__ __forceinline__ void gemm2_load_chunk(uint32_t bufb, int row0, int bcol0,
                                                 size_t wbase, int k0, int tid) {
    ld_t128x64(bufb,                &g_Xhi[(size_t)row0 * N_DIM + k0], tid);
    ld_t128x64(bufb + G2_TILE,      &g_Xlo[(size_t)row0 * N_DIM + k0], tid);
    ld_t128x64(bufb + 2 * G2_TILE,  &g_Whi[wbase + (size_t)bcol0 * N_DIM + k0], tid);
    ld_t128x64(bufb + 3 * G2_TILE,  &g_Wlo[wbase + (size_t)bcol0 * N_DIM + k0], tid);
    CP_COMMIT;
}
#endif

__global__ __launch_bounds__(256) __cluster_dims__(2, 1, 1) void qkv_gemm_tc()
{
#if HAS_TC
    extern __shared__ char smem[];
    const uint32_t sb = smem_u32(smem);
    const uint32_t bufbase = (sb + 1024 + 1023) & ~1023u;
    const int tid = threadIdx.x;
    const int lane = tid & 31;
    const int wid = tid >> 5;
    const int rank = blockIdx.x;              // cluster rank (cluster along x)
    const int colb = blockIdx.y & 15;
    const int rpair = blockIdx.y >> 4;
    const int col0 = colb * 256;              // pair's N origin
    const int row0 = rpair * 256 + rank * 128;  // this CTA's M origin
    const int bcol0 = col0 + rank * 128;      // this CTA's B cols
    const int z = blockIdx.z;
    const size_t wbase = (size_t)z * N_DIM * N_DIM;

    if (wid == 0) {
        asm volatile("tcgen05.alloc.cta_group::2.sync.aligned.shared::cta.b32 [%0], %1;"
                     :: "r"(sb), "r"(256u) : "memory");
    }
    if (tid == 0) {
        mbar_init(sb + 16, 1);
        mbar_init(sb + 24, 1);
    }
    __syncthreads();
    uint32_t tmem;
    asm volatile("ld.shared.b32 %0, [%1];" : "=r"(tmem) : "r"(sb));

    gemm2_load_chunk(bufbase, row0, bcol0, wbase, 0, tid);
    gemm2_load_chunk(bufbase + G2_BUFSZ, row0, bcol0, wbase, 64, tid);

    int wcnt[2] = {0, 0};
    for (int it = 0; it < G2_NCH; it++) {
        const int b = it & 1;
        const uint32_t bufb = bufbase + b * G2_BUFSZ;
        // chunk it resident locally
        asm volatile("cp.async.wait_group 1;");
        asm volatile("fence.proxy.async.shared::cta;" ::: "memory");
        // both CTAs' chunks resident cluster-wide
        CLUSTER_BAR();

        if (rank == 0 && wid == 0 && elect1()) {
            uint64_t dA[2] = {mk_desc(bufb), mk_desc(bufb + G2_TILE)};
            uint64_t dB[2] = {mk_desc(bufb + 2 * G2_TILE), mk_desc(bufb + 3 * G2_TILE)};
            const int ca[3] = {0, 0, 1};
            const int cb[3] = {0, 1, 0};
#pragma unroll
            for (int c = 0; c < 3; c++)
#pragma unroll
                for (int k8 = 0; k8 < 4; k8++) {
                    uint32_t en = !(it == 0 && c == 0 && k8 == 0);
                    mma_ss_cg2(tmem, dA[ca[c]] + k8 * 2, dB[cb[c]] + k8 * 2,
                               G2_IDESC, en);
                }
            asm volatile(
                "tcgen05.commit.cta_group::2.mbarrier::arrive::one.shared::cluster"
                ".multicast::cluster.b64 [%0], %1;"
                :: "r"(sb + 16 + b * 8), "h"((uint16_t)3) : "memory");
        }

        if (it + 2 < G2_NCH) {
            // mma(it) done reading BOTH CTAs' buffer b -> safe to refill
            mbar_wait(sb + 16 + b * 8, wcnt[b] & 1);
            wcnt[b]++;
            asm volatile("fence.proxy.async.shared::cta;" ::: "memory");
            gemm2_load_chunk(bufb, row0, bcol0, wbase, (it + 2) * 64, tid);
        }
    }
    mbar_wait(sb + 16, 1);
    mbar_wait(sb + 24, 1);
    asm volatile("tcgen05.fence::after_thread_sync;" ::: "memory");
    __syncthreads();

    // epilogue — this CTA's 128 rows x 256 cols live in its own TMEM
    const int sp = wid & 3;
    const int ch = wid >> 2;
    float* T = (float*)(smem + (bufbase - sb)) + wid * (32 * 33);
#pragma unroll 1
    for (int cbk = 0; cbk < 4; cbk++) {
        int c0 = ch * 128 + cbk * 32;
        uint32_t r[32];
        LDTM32(r, tmem + c0);
        asm volatile("tcgen05.wait::ld.sync.aligned;" ::: "memory");
        if (z == 2) {
            // VT direct: lane = row (m), reg j = col (h*128+d)
            int m = row0 + sp * 32 + lane;
#pragma unroll
            for (int j = 0; j < 32; j++) {
                float v = __uint_as_float(r[j]);
                __nv_bfloat16 hi = __float2bfloat16_rn(v);
                __nv_bfloat16 lo = __float2bfloat16_rn(v - __bfloat162float(hi));
                int col = col0 + c0 + j;
                size_t o = ((size_t)(col >> 7) * D_DIM + (col & 127)) * L_DIM +
                           P_POS + m;
                g_VThi[o] = hi;
                g_VTlo[o] = lo;
            }
        } else {
#pragma unroll
            for (int j = 0; j < 32; j++) T[lane * 33 + j] = __uint_as_float(r[j]);
            __syncwarp();
#pragma unroll
            for (int rr = 0; rr < 32; rr++) {
                float v = T[rr * 33 + lane];
                __nv_bfloat16 hi = __float2bfloat16_rn(v);
                __nv_bfloat16 lo = __float2bfloat16_rn(v - __bfloat162float(hi));
                int row = row0 + sp * 32 + rr;
                int col = col0 + c0 + lane;
                if (z == 0) {
                    size_t o = (size_t)row * N_DIM + col;
                    g_Qhi[o] = hi;
                    g_Qlo[o] = lo;
                } else {
                    size_t o = ((size_t)(col >> 7) * L_DIM + P_POS + row) * D_DIM +
                               (col & 127);
                    g_KAhi[o] = hi;
                    g_KAlo[o] = lo;
                }
            }
            __syncwarp();
        }
    }
    __syncthreads();
    if (wid == 0) {
        asm volatile("tcgen05.relinquish_alloc_permit.cta_group::2.sync.aligned;");
        asm volatile("tcgen05.dealloc.cta_group::2.sync.aligned.b32 %0, %1;"
                     :: "r"(tmem), "r"(256u));
    }
    CLUSTER_BAR();
#endif
}

// ---------------------------------------------------------------------------
// Pre-pass: K cache -> g_KA [h][l][d] hi/lo (cache rows only; fresh from GEMM)
// ---------------------------------------------------------------------------
__global__ __launch_bounds__(256) void build_k_kernel(const float* __restrict__ cacheK)
{
    size_t idx = ((size_t)blockIdx.x * 256 + threadIdx.x) * 8;
    size_t rem = idx % ((size_t)L_DIM * D_DIM);
    int l = (int)(rem / D_DIM);
    if (l >= P_POS && l < P_POS + M_DIM) return;  // GEMM epilogue wrote these
    const float* src = &cacheK[idx];
    float4 f0 = *(const float4*)src;
    float4 f1 = *(const float4*)(src + 4);
    uint4 hi, lo;
    hi.x = split2(f0.x, f0.y, lo.x);
    hi.y = split2(f0.z, f0.w, lo.y);
    hi.z = split2(f1.x, f1.y, lo.z);
    hi.w = split2(f1.z, f1.w, lo.w);
    *(uint4*)&g_KAhi[idx] = hi;
    *(uint4*)&g_KAlo[idx] = lo;
}

// ---------------------------------------------------------------------------
// Pre-pass: V cache transposed -> g_VT [h][d][l] (cache rows only)
// ---------------------------------------------------------------------------
__global__ __launch_bounds__(256) void build_vt_kernel(const float* __restrict__ cacheV)
{
    const int l0 = blockIdx.x * 64;
    if (l0 >= P_POS && l0 < P_POS + M_DIM) return;  // fresh: GEMM wrote VT directly
    __shared__ __nv_bfloat16 Shi[64][65];
    __shared__ __nv_bfloat16 Slo[64][65];
    const int d0 = blockIdx.y * 64;
    const int h = blockIdx.z;
    const int tid = threadIdx.x;

#pragma unroll
    for (int j = 0; j < 16; j++) {
        int idx = tid + j * 256;
        int lr = idx >> 6, dc = idx & 63;
        float v = cacheV[((size_t)h * L_DIM + l0 + lr) * D_DIM + d0 + dc];
        __nv_bfloat16 hi = __float2bfloat16_rn(v);
        __nv_bfloat16 lo = __float2bfloat16_rn(v - __bfloat162float(hi));
        Shi[lr][dc] = hi;
        Slo[lr][dc] = lo;
    }
    __syncthreads();
#pragma unroll
    for (int j = 0; j < 16; j++) {
        int idx = tid + j * 256;
        int dr = idx >> 6, lc = idx & 63;
        size_t o = ((size_t)h * D_DIM + d0 + dr) * L_DIM + l0 + lc;
        g_VThi[o] = Shi[lc][dr];
        g_VTlo[o] = Slo[lc][dr];
    }
}

// ---------------------------------------------------------------------------
// tcgen05 attention (unchanged from R7): BL=64, K/V/S double-buffered.
// TMEM: S0@0, S1@64, O@128, Phi@256, Plo@288.
// ---------------------------------------------------------------------------
#define A_NCH 64
#define AQ_HI 0
#define AQ_LO 32768
#define AK_BASE 65536
#define AV_BASE 131072
#define ATTN_SMEM (2112 + 1024 + 196608)
#define S_IDESC 0x8100490u
#define PV_IDESC 0x8200490u
#define TM_S 0
#define TM_O 128
#define TM_PHI 256
#define TM_PLO 288

__global__ __launch_bounds__(256) void attn_tc(float* __restrict__ out)
{
#if HAS_TC
    extern __shared__ char smem[];
    const uint32_t sb = smem_u32(smem);
    const uint32_t db = (sb + 1088 + 1023) & ~1023u;
    float* rsum_s = (float*)(smem + 64);
    const int tid = threadIdx.x;
    const int lane = tid & 31;
    const int wid = tid >> 5;
    const int sp = wid & 3;
    const int ch = wid >> 2;
    const int m0 = blockIdx.x * 128;
    const int h = blockIdx.y;

    const uint32_t mbS = sb + 16;
    const uint32_t mbP = sb + 24;

    if (wid == 0) {
        asm volatile("tcgen05.alloc.cta_group::1.sync.aligned.shared::cta.b32 [%0], %1;"
                     :: "r"(sb), "r"(512u) : "memory");
    }
    if (tid == 0) {
        mbar_init(mbS, 1);
        mbar_init(mbP, 1);
    }
    __syncthreads();
    uint32_t tmem;
    asm volatile("ld.shared.b32 %0, [%1];" : "=r"(tmem) : "r"(sb));

    const __nv_bfloat16* KAh = &g_KAhi[(size_t)h * L_DIM * D_DIM];
    const __nv_bfloat16* KAl = &g_KAlo[(size_t)h * L_DIM * D_DIM];
    const __nv_bfloat16* VTh = &g_VThi[(size_t)h * D_DIM * L_DIM];
    const __nv_bfloat16* VTl = &g_VTlo[(size_t)h * D_DIM * L_DIM];

    const uint64_t DOFF_Q[8] = {0, 2, 4, 6, 1024, 1026, 1028, 1030};
    const uint64_t DOFF_K[8] = {0, 2, 4, 6, 512, 514, 516, 518};
    const int ca3[3] = {0, 0, 1};
    const int cb3[3] = {0, 1, 0};

    ld_tile(db + AQ_HI, &g_Qhi[(size_t)m0 * N_DIM + h * D_DIM], N_DIM, tid);
    ld_tile(db + AQ_LO, &g_Qlo[(size_t)m0 * N_DIM + h * D_DIM], N_DIM, tid);
    ld_tile_k64(db + AK_BASE, &KAh[0], D_DIM, tid);
    ld_tile_k64(db + AK_BASE + 16384, &KAl[0], D_DIM, tid);
    CP_COMMIT;
    ld_tile_k64(db + AK_BASE + 32768, &KAh[(size_t)64 * D_DIM], D_DIM, tid);
    ld_tile_k64(db + AK_BASE + 49152, &KAl[(size_t)64 * D_DIM], D_DIM, tid);
    CP_COMMIT;
    ld_tile_v64(db + AV_BASE, &VTh[0], L_DIM, tid);
    ld_tile_v64(db + AV_BASE + 16384, &VTl[0], L_DIM, tid);
    CP_COMMIT;

    const uint64_t dQ0 = mk_desc(db + AQ_HI);
    const uint64_t dQ1 = mk_desc(db + AQ_LO);

    asm volatile("cp.async.wait_group 2;");
    asm volatile("fence.proxy.async.shared::cta;" ::: "memory");
    __syncthreads();
    if (wid == 0 && elect1()) {
        asm volatile("fence.proxy.async.shared::cta;" ::: "memory");
        uint64_t dQ[2] = {dQ0, dQ1};
        uint64_t dK[2] = {mk_desc(db + AK_BASE), mk_desc(db + AK_BASE + 16384)};
#pragma unroll
        for (int c = 0; c < 3; c++)
#pragma unroll
            for (int k8 = 0; k8 < 8; k8++)
                mma_ss(tmem + TM_S, dQ[ca3[c]] + DOFF_Q[k8], dK[cb3[c]] + DOFF_K[k8],
                       S_IDESC, !(c == 0 && k8 == 0));
        asm volatile(
            "tcgen05.commit.cta_group::1.mbarrier::arrive::one.shared::cluster.b64 [%0];"
            :: "r"(mbS) : "memory");
    }

    float rsum = 0.0f;

    for (int it = 0; it < A_NCH; it++) {
        mbar_wait(mbS, it & 1);
        asm volatile("tcgen05.fence::after_thread_sync;" ::: "memory");

        if (it < A_NCH - 1) {
            asm volatile("cp.async.wait_group 1;");
            asm volatile("fence.proxy.async.shared::cta;" ::: "memory");
            __syncthreads();
            if (wid == 0 && elect1()) {
                asm volatile("fence.proxy.async.shared::cta;" ::: "memory");
                const uint32_t kb = db + AK_BASE + ((it + 1) & 1) * 32768;
                uint64_t dQ[2] = {dQ0, dQ1};
                uint64_t dK[2] = {mk_desc(kb), mk_desc(kb + 16384)};
                const uint32_t sdst = tmem + TM_S + ((it + 1) & 1) * 64;
#pragma unroll
                for (int c = 0; c < 3; c++)
#pragma unroll
                    for (int k8 = 0; k8 < 8; k8++)
                        mma_ss(sdst, dQ[ca3[c]] + DOFF_Q[k8], dK[cb3[c]] + DOFF_K[k8],
                               S_IDESC, !(c == 0 && k8 == 0));
                asm volatile(
                    "tcgen05.commit.cta_group::1.mbarrier::arrive::one.shared::cluster.b64 [%0];"
                    :: "r"(mbS) : "memory");
            }
        }
        if (it + 2 < A_NCH) {
            const uint32_t kb = db + AK_BASE + (it & 1) * 32768;
            ld_tile_k64(kb, &KAh[(size_t)(it + 2) * 64 * D_DIM], D_DIM, tid);
            ld_tile_k64(kb + 16384, &KAl[(size_t)(it + 2) * 64 * D_DIM], D_DIM, tid);
            CP_COMMIT;
        }
        if (it > 0) {
            mbar_wait(mbP, (it - 1) & 1);
            asm volatile("tcgen05.fence::after_thread_sync;" ::: "memory");
        }
        if (it + 1 < A_NCH) {
            const uint32_t vb = db + AV_BASE + ((it + 1) & 1) * 32768;
            ld_tile_v64(vb, &VTh[(size_t)(it + 1) * 64], L_DIM, tid);
            ld_tile_v64(vb + 16384, &VTl[(size_t)(it + 1) * 64], L_DIM, tid);
            CP_COMMIT;
        }
        {
            const uint32_t sbuf = tmem + TM_S + (it & 1) * 64;
            uint32_t s0[32];
            LDTM32(s0, sbuf + ch * 32);
            asm volatile("tcgen05.wait::ld.sync.aligned;" ::: "memory");
            uint32_t ph[16], pl[16];
#pragma unroll
            for (int t = 0; t < 16; t++) {
                float e0 = __expf(__uint_as_float(s0[2 * t]));
                float e1 = __expf(__uint_as_float(s0[2 * t + 1]));
                rsum += e0 + e1;
                ph[t] = split2(e0, e1, pl[t]);
            }
            uint32_t wofs = ((uint32_t)sp << 21) + ch * 16;
            STTM16(tmem + TM_PHI + wofs, ph);
            STTM16(tmem + TM_PLO + wofs, pl);
            asm volatile("tcgen05.wait::st.sync.aligned;" ::: "memory");
        }
        asm volatile("tcgen05.fence::before_thread_sync;" ::: "memory");
        if (it + 2 < A_NCH)      asm volatile("cp.async.wait_group 2;");
        else if (it + 1 < A_NCH) asm volatile("cp.async.wait_group 1;");
        else                     asm volatile("cp.async.wait_group 0;");
        asm volatile("fence.proxy.async.shared::cta;" ::: "memory");
        __syncthreads();
        if (wid == 0 && elect1()) {
            asm volatile("tcgen05.fence::after_thread_sync;" ::: "memory");
            asm volatile("fence.proxy.async.shared::cta;" ::: "memory");
            const uint32_t vb = db + AV_BASE + (it & 1) * 32768;
            uint64_t dV[2] = {mk_desc(vb), mk_desc(vb + 16384)};
            const uint32_t pa[3] = {TM_PHI, TM_PHI, TM_PLO};
            const int pb[3] = {0, 1, 0};
#pragma unroll
            for (int c = 0; c < 3; c++)
#pragma unroll
                for (int k8 = 0; k8 < 4; k8++)
                    mma_ts(tmem + TM_O, tmem + pa[c] + k8 * 8, dV[pb[c]] + k8 * 2,
                           PV_IDESC, !(it == 0 && c == 0 && k8 == 0));
            asm volatile(
                "tcgen05.commit.cta_group::1.mbarrier::arrive::one.shared::cluster.b64 [%0];"
                :: "r"(mbP) : "memory");
        }
    }
    mbar_wait(mbP, (A_NCH - 1) & 1);
    asm volatile("tcgen05.fence::after_thread_sync;" ::: "memory");

    rsum_s[(sp * 32 + lane) * 2 + ch] = rsum;
    __syncthreads();

    {
        uint32_t o0[32], o1[32];
        LDTM32(o0, tmem + TM_O + ch * 64);
        LDTM32(o1, tmem + TM_O + ch * 64 + 32);
        asm volatile("tcgen05.wait::ld.sync.aligned;" ::: "memory");
        int row = sp * 32 + lane;
        float inv = 1.0f / (rsum_s[row * 2 + 0] + rsum_s[row * 2 + 1]);
        float* T = (float*)(smem + (db - sb)) + wid * (32 * 65);
#pragma unroll
        for (int j = 0; j < 32; j++) T[lane * 65 + j] = __uint_as_float(o0[j]) * inv;
#pragma unroll
        for (int j = 0; j < 32; j++) T[lane * 65 + 32 + j] = __uint_as_float(o1[j]) * inv;
        __syncwarp();
#pragma unroll
        for (int r = 0; r < 32; r++) {
            size_t o = (size_t)(m0 + sp * 32 + r) * N_DIM + h * D_DIM + ch * 64;
            out[o + lane] = T[r * 65 + lane];
            out[o + 32 + lane] = T[r * 65 + 32 + lane];
        }
    }
    __syncthreads();
    if (wid == 0) {
        asm volatile("tcgen05.dealloc.cta_group::1.sync.aligned.b32 %0, %1;"
                     :: "r"(tmem), "r"(512u));
    }
#endif
}

// ---------------------------------------------------------------------------
extern "C" void kernel_launch(void* const* d_in, const int* in_sizes, int n_in,
                              void* d_out, int out_size)
{
    const float* X = (const float*)d_in[0];
    const float* Wq = (const float*)d_in[1];
    const float* Wk = (const float*)d_in[2];
    const float* Wv = (const float*)d_in[3];
    const float* cK = (const float*)d_in[4];
    const float* cV = (const float*)d_in[5];
    float* out = (float*)d_out;

    cudaFuncSetAttribute(qkv_gemm_tc,
                         cudaFuncAttributeMaxDynamicSharedMemorySize, TC2_SMEM);
    cudaFuncSetAttribute(attn_tc,
                         cudaFuncAttributeMaxDynamicSharedMemorySize, ATTN_SMEM);

    convert_x_kernel<<<2048, 256>>>(X);
    convert_w_kernel<<<dim3(64, 64, 3), 256>>>(Wq, Wk, Wv);
    qkv_gemm_tc<<<dim3(2, 64, 3), 256, TC2_SMEM>>>();
    build_k_kernel<<<8192, 256>>>(cK);
    build_vt_kernel<<<dim3(64, 2, 32), 256>>>(cV);
    attn_tc<<<dim3(8, 32), 256, ATTN_SMEM>>>(out);
}

// round 9
// speedup vs baseline: 1.0371x; 1.0371x over previous
#include <cuda_runtime.h>
#include <cuda_bf16.h>
#include <math.h>
#include <stdint.h>

#define M_DIM 1024
#define N_DIM 4096
#define D_DIM 128
#define H_DIM 32
#define P_POS 2048
#define L_DIM 4096

// --- arch-specific feature gate (tcgen05 only legal in sm_103a-specific pass)
#if defined(__CUDA_ARCH__)
#if defined(__CUDA_ARCH_FEAT_SM103_ALL)
#define HAS_TC 1
#elif defined(__CUDA_ARCH_SPECIFIC__) && (__CUDA_ARCH_SPECIFIC__ == 1030)
#define HAS_TC 1
#endif
#endif
#ifndef HAS_TC
#define HAS_TC 0
#endif

// bf16-split operands.
__device__ __nv_bfloat16 g_Xhi[M_DIM * (size_t)N_DIM];
__device__ __nv_bfloat16 g_Xlo[M_DIM * (size_t)N_DIM];
__device__ __nv_bfloat16 g_Whi[3 * (size_t)N_DIM * N_DIM];
__device__ __nv_bfloat16 g_Wlo[3 * (size_t)N_DIM * N_DIM];
// Q projection output, bf16 hi/lo, [M][N] row-major.
__device__ __nv_bfloat16 g_Qhi[M_DIM * (size_t)N_DIM];
__device__ __nv_bfloat16 g_Qlo[M_DIM * (size_t)N_DIM];
// Merged cache: K_all [H][L][D], V_all transposed [H][D][L].
// Fresh region [P, P+M) written directly by the GEMM epilogue.
__device__ __nv_bfloat16 g_KAhi[(size_t)H_DIM * L_DIM * D_DIM];
__device__ __nv_bfloat16 g_KAlo[(size_t)H_DIM * L_DIM * D_DIM];
__device__ __nv_bfloat16 g_VThi[(size_t)H_DIM * D_DIM * L_DIM];
__device__ __nv_bfloat16 g_VTlo[(size_t)H_DIM * D_DIM * L_DIM];

// ---------------------------------------------------------------------------
// helpers
// ---------------------------------------------------------------------------
__device__ __forceinline__ uint32_t smem_u32(const void* p) {
    return (uint32_t)__cvta_generic_to_shared(p);
}
__device__ __forceinline__ void cp16s(uint32_t s, const void* g) {
    asm volatile("cp.async.cg.shared.global [%0], [%1], 16;" :: "r"(s), "l"(g));
}
#define CP_COMMIT asm volatile("cp.async.commit_group;")

__device__ __forceinline__ uint32_t split2(float a, float b, uint32_t& lo) {
    __nv_bfloat16 ah = __float2bfloat16_rn(a);
    __nv_bfloat16 bh = __float2bfloat16_rn(b);
    __nv_bfloat16 al = __float2bfloat16_rn(a - __bfloat162float(ah));
    __nv_bfloat16 bl = __float2bfloat16_rn(b - __bfloat162float(bh));
    lo = (uint32_t)__bfloat16_as_ushort(al) | ((uint32_t)__bfloat16_as_ushort(bl) << 16);
    return (uint32_t)__bfloat16_as_ushort(ah) | ((uint32_t)__bfloat16_as_ushort(bh) << 16);
}

#define SWZ(x) ((x) ^ ((((uint32_t)(x)) >> 3) & 0x70))
#define SWZ64(x) ((x) ^ ((((uint32_t)(x)) >> 3) & 0x30))

#if HAS_TC
__device__ __forceinline__ uint32_t elect1() {
    uint32_t p;
    asm volatile("{\n\t.reg .pred p;\n\telect.sync _|p, 0xFFFFFFFF;\n\t"
                 "selp.b32 %0, 1, 0, p;\n\t}" : "=r"(p));
    return p;
}
__device__ __forceinline__ void mbar_init(uint32_t m, uint32_t cnt) {
    asm volatile("mbarrier.init.shared.b64 [%0], %1;" :: "r"(m), "r"(cnt) : "memory");
}
__device__ __forceinline__ void mbar_wait(uint32_t m, uint32_t parity) {
    uint32_t done;
    asm volatile(
        "{\n\t.reg .pred p;\n\t"
        "mbarrier.try_wait.parity.acquire.cta.shared::cta.b64 p, [%1], %2;\n\t"
        "selp.b32 %0, 1, 0, p;\n\t}"
        : "=r"(done) : "r"(m), "r"(parity) : "memory");
    if (!done) {
        asm volatile(
            "{\n\t.reg .pred P1;\n\t"
            "WL_%=:\n\t"
            "mbarrier.try_wait.parity.acquire.cta.shared::cta.b64 P1, [%0], %1, 0x989680;\n\t"
            "@P1 bra.uni WD_%=;\n\t"
            "bra.uni WL_%=;\n\t"
            "WD_%=:\n\t}"
            :: "r"(m), "r"(parity) : "memory");
    }
}
// SW128 K-major descriptor (layout 2, LBO=1, SBO=64)
__device__ __forceinline__ uint64_t mk_desc(uint32_t addr) {
    const uint64_t base = (uint64_t(2) << 61) | (uint64_t(1) << 46) |
                          (uint64_t(64) << 32) | (uint64_t(1) << 16);
    return base | ((uint64_t)(addr >> 4) & 0x3FFF);
}
// SW64 K-major descriptor (layout 4, LBO=1, SBO=32) — 64-byte rows
__device__ __forceinline__ uint64_t mk_desc64(uint32_t addr) {
    const uint64_t base = (uint64_t(4) << 61) | (uint64_t(1) << 46) |
                          (uint64_t(32) << 32) | (uint64_t(1) << 16);
    return base | ((uint64_t)(addr >> 4) & 0x3FFF);
}
__device__ __forceinline__ void mma_ss(uint32_t d, uint64_t ad, uint64_t bd,
                                       uint32_t idesc, uint32_t en) {
    asm volatile(
        "{\n\t.reg .pred p;\n\t"
        "setp.ne.u32 p, %4, 0;\n\t"
        "tcgen05.mma.cta_group::1.kind::f16 [%0], %1, %2, %3, {%5,%5,%5,%5}, p;\n\t}"
        :: "r"(d), "l"(ad), "l"(bd), "r"(idesc), "r"(en), "r"(0u) : "memory");
}
__device__ __forceinline__ void mma_ts(uint32_t d, uint32_t at, uint64_t bd,
                                       uint32_t idesc, uint32_t en) {
    asm volatile(
        "{\n\t.reg .pred p;\n\t"
        "setp.ne.u32 p, %4, 0;\n\t"
        "tcgen05.mma.cta_group::1.kind::f16 [%0], [%1], %2, %3, {%5,%5,%5,%5}, p;\n\t}"
        :: "r"(d), "r"(at), "l"(bd), "r"(idesc), "r"(en), "r"(0u) : "memory");
}
#define LDTM32(r, a)                                                            \
    asm volatile(                                                               \
        "tcgen05.ld.sync.aligned.32x32b.x32.b32 "                               \
        "{%0,%1,%2,%3,%4,%5,%6,%7,%8,%9,%10,%11,%12,%13,%14,%15,"               \
        "%16,%17,%18,%19,%20,%21,%22,%23,%24,%25,%26,%27,%28,%29,%30,%31},[%32];" \
        : "=r"((r)[0]), "=r"((r)[1]), "=r"((r)[2]), "=r"((r)[3]),               \
          "=r"((r)[4]), "=r"((r)[5]), "=r"((r)[6]), "=r"((r)[7]),               \
          "=r"((r)[8]), "=r"((r)[9]), "=r"((r)[10]), "=r"((r)[11]),             \
          "=r"((r)[12]), "=r"((r)[13]), "=r"((r)[14]), "=r"((r)[15]),           \
          "=r"((r)[16]), "=r"((r)[17]), "=r"((r)[18]), "=r"((r)[19]),           \
          "=r"((r)[20]), "=r"((r)[21]), "=r"((r)[22]), "=r"((r)[23]),           \
          "=r"((r)[24]), "=r"((r)[25]), "=r"((r)[26]), "=r"((r)[27]),           \
          "=r"((r)[28]), "=r"((r)[29]), "=r"((r)[30]), "=r"((r)[31])            \
        : "r"(a))
#define STTM16(a, r)                                                            \
    asm volatile(                                                               \
        "tcgen05.st.sync.aligned.32x32b.x16.b32 [%0], "                         \
        "{%1,%2,%3,%4,%5,%6,%7,%8,%9,%10,%11,%12,%13,%14,%15,%16};"             \
        :: "r"(a),                                                              \
           "r"((r)[0]), "r"((r)[1]), "r"((r)[2]), "r"((r)[3]),                  \
           "r"((r)[4]), "r"((r)[5]), "r"((r)[6]), "r"((r)[7]),                  \
           "r"((r)[8]), "r"((r)[9]), "r"((r)[10]), "r"((r)[11]),                \
           "r"((r)[12]), "r"((r)[13]), "r"((r)[14]), "r"((r)[15])               \
        : "memory")

// 128x128 bf16 tile (atom-blocked K-major SW128, 256B logical rows)
__device__ __forceinline__ void ld_tile(uint32_t sdst, const __nv_bfloat16* g,
                                        size_t stride, int tid) {
#pragma unroll
    for (int j = 0; j < 8; j++) {
        int u = tid + j * 256;
        int r = u >> 4;
        int c8 = u & 15;
        uint32_t so = (uint32_t)(((r >> 3) + (c8 >> 3) * 16) * 1024 +
                                 (r & 7) * 128 + (c8 & 7) * 16);
        cp16s(sdst + SWZ(so), g + (size_t)r * stride + c8 * 8);
    }
}
// 64x128 bf16 tile (atom-blocked, 8 atoms per 128B-col-block)
__device__ __forceinline__ void ld_tile_k64(uint32_t sdst, const __nv_bfloat16* g,
                                            size_t stride, int tid) {
#pragma unroll
    for (int j = 0; j < 4; j++) {
        int u = tid + j * 256;
        int r = u >> 4;
        int c8 = u & 15;
        uint32_t so = (uint32_t)(((r >> 3) + (c8 >> 3) * 8) * 1024 +
                                 (r & 7) * 128 + (c8 & 7) * 16);
        cp16s(sdst + SWZ(so), g + (size_t)r * stride + c8 * 8);
    }
}
// 128x64 bf16 tile (128B rows, single atom column)
__device__ __forceinline__ void ld_tile_v64(uint32_t sdst, const __nv_bfloat16* g,
                                            size_t stride, int tid) {
#pragma unroll
    for (int j = 0; j < 4; j++) {
        int u = tid + j * 256;
        int r = u >> 3;
        int c8 = u & 7;
        uint32_t so = (uint32_t)((r >> 3) * 1024 + (r & 7) * 128 + c8 * 16);
        cp16s(sdst + SWZ(so), g + (size_t)r * stride + c8 * 8);
    }
}
// NROWSx32k bf16 tile with 64-byte rows (SW64 atoms, stacked vertically).
// NITER = NROWS*4/256.
template <int NITER>
__device__ __forceinline__ void ld_sw64(uint32_t sdst, const __nv_bfloat16* g,
                                        int tid) {
#pragma unroll
    for (int j = 0; j < NITER; j++) {
        int u = tid + j * 256;
        int r = u >> 2;
        int c4 = u & 3;
        uint32_t so = (uint32_t)((r >> 3) * 512) + SWZ64((r & 7) * 64 + c4 * 16);
        cp16s(sdst + so, g + (size_t)r * N_DIM + c4 * 8);
    }
}
#endif  // HAS_TC

// ---------------------------------------------------------------------------
// Pre-pass: X fp32 -> bf16 hi/lo
// ---------------------------------------------------------------------------
__global__ __launch_bounds__(256) void convert_x_kernel(const float* __restrict__ X) {
    size_t i0 = ((size_t)blockIdx.x * 256 + threadIdx.x) * 8;
    float4 f0 = *(const float4*)&X[i0];
    float4 f1 = *(const float4*)&X[i0 + 4];
    uint4 hi, lo;
    hi.x = split2(f0.x, f0.y, lo.x);
    hi.y = split2(f0.z, f0.w, lo.y);
    hi.z = split2(f1.x, f1.y, lo.z);
    hi.w = split2(f1.z, f1.w, lo.w);
    *(uint4*)&g_Xhi[i0] = hi;
    *(uint4*)&g_Xlo[i0] = lo;
}

// ---------------------------------------------------------------------------
// Pre-pass: W [k][n] fp32 -> WT [n][k] bf16 hi/lo
// ---------------------------------------------------------------------------
__global__ __launch_bounds__(256) void convert_w_kernel(
    const float* __restrict__ Wq, const float* __restrict__ Wk,
    const float* __restrict__ Wv)
{
    __shared__ float sm[64][65];
    const float* W = (blockIdx.z == 0) ? Wq : (blockIdx.z == 1) ? Wk : Wv;
    const size_t wo = (size_t)blockIdx.z * N_DIM * N_DIM;
    const int k0 = blockIdx.x * 64;
    const int n0 = blockIdx.y * 64;
    const int tid = threadIdx.x;

#pragma unroll
    for (int j = 0; j < 16; j++) {
        int idx = tid + j * 256;
        int kr = idx >> 6, nc = idx & 63;
        sm[kr][nc] = W[(size_t)(k0 + kr) * N_DIM + n0 + nc];
    }
    __syncthreads();
#pragma unroll
    for (int j = 0; j < 8; j++) {
        int idx = tid + j * 256;
        int ni = idx >> 5, kp = idx & 31;
        float a = sm[kp * 2][ni];
        float b = sm[kp * 2 + 1][ni];
        uint32_t lo, hi = split2(a, b, lo);
        size_t o = wo + (size_t)(n0 + ni) * N_DIM + k0 + kp * 2;
        *(uint32_t*)&g_Whi[o] = hi;
        *(uint32_t*)&g_Wlo[o] = lo;
    }
}

// ---------------------------------------------------------------------------
// cg1 tcgen05 bf16x3-split GEMM, tile M=128 x N=512, K-chunk 32 (SW64).
// TMEM: D0 @ cols 0-255, D1 @ 256-511.
// Epilogue: z=0 -> g_Q row-major; z=1 -> g_KA fresh rows; z=2 -> g_VT direct.
// ---------------------------------------------------------------------------
#define G3_AH 8192
#define G3_BH 32768
#define G3_BUFSZ (2 * G3_AH + 2 * G3_BH)       // 81920
#define TC_SMEM (2048 + 2 * G3_BUFSZ)          // 165888
#define G_IDESC 0x8400490u                     // f32 acc, bf16, N=256, M=128
#define G3_NCH 128

#if HAS_TC
__device__ __forceinline__ void gemm3_load_chunk(uint32_t bufb, int row0, int col0,
                                                 size_t wbase, int k0, int tid) {
    ld_sw64<2>(bufb,               &g_Xhi[(size_t)row0 * N_DIM + k0], tid);
    ld_sw64<2>(bufb + G3_AH,       &g_Xlo[(size_t)row0 * N_DIM + k0], tid);
    ld_sw64<8>(bufb + 2 * G3_AH,   &g_Whi[wbase + (size_t)col0 * N_DIM + k0], tid);
    ld_sw64<8>(bufb + 2 * G3_AH + G3_BH,
               &g_Wlo[wbase + (size_t)col0 * N_DIM + k0], tid);
    CP_COMMIT;
}
#endif

__global__ __launch_bounds__(256) void qkv_gemm_tc()
{
#if HAS_TC
    extern __shared__ char smem[];
    const uint32_t sb = smem_u32(smem);
    const uint32_t bufbase = (sb + 1024 + 1023) & ~1023u;
    const int tid = threadIdx.x;
    const int lane = tid & 31;
    const int wid = tid >> 5;
    const int row0 = blockIdx.y * 128;
    const int col0 = blockIdx.x * 512;
    const int z = blockIdx.z;
    const size_t wbase = (size_t)z * N_DIM * N_DIM;

    if (wid == 0) {
        asm volatile("tcgen05.alloc.cta_group::1.sync.aligned.shared::cta.b32 [%0], %1;"
                     :: "r"(sb), "r"(512u) : "memory");
    }
    if (tid == 0) {
        mbar_init(sb + 16, 1);
        mbar_init(sb + 24, 1);
    }
    __syncthreads();
    uint32_t tmem;
    asm volatile("ld.shared.b32 %0, [%1];" : "=r"(tmem) : "r"(sb));

    gemm3_load_chunk(bufbase, row0, col0, wbase, 0, tid);
    gemm3_load_chunk(bufbase + G3_BUFSZ, row0, col0, wbase, 32, tid);

    int wcnt[2] = {0, 0};
    for (int it = 0; it < G3_NCH; it++) {
        const int b = it & 1;
        const uint32_t bufb = bufbase + b * G3_BUFSZ;
        asm volatile("cp.async.wait_group 1;");
        asm volatile("fence.proxy.async.shared::cta;" ::: "memory");
        __syncthreads();

        if (wid == 0 && elect1()) {
            asm volatile("fence.proxy.async.shared::cta;" ::: "memory");
            uint64_t dA[2] = {mk_desc64(bufb), mk_desc64(bufb + G3_AH)};
            uint64_t dB[2] = {mk_desc64(bufb + 2 * G3_AH),
                              mk_desc64(bufb + 2 * G3_AH + G3_BH)};
            const int ca[3] = {0, 0, 1};
            const int cb[3] = {0, 1, 0};
#pragma unroll
            for (int c = 0; c < 3; c++)
#pragma unroll
                for (int ks = 0; ks < 2; ks++) {
                    uint32_t en = !(it == 0 && c == 0 && ks == 0);
                    // D0: B rows 0-255 ; D1: B rows 256-511 (+16KB = 1024 units)
                    mma_ss(tmem, dA[ca[c]] + ks * 2, dB[cb[c]] + ks * 2,
                           G_IDESC, en);
                    mma_ss(tmem + 256, dA[ca[c]] + ks * 2, dB[cb[c]] + 1024 + ks * 2,
                           G_IDESC, en);
                }
            asm volatile(
                "tcgen05.commit.cta_group::1.mbarrier::arrive::one.shared::cluster.b64 [%0];"
                :: "r"(sb + 16 + b * 8) : "memory");
        }

        if (it + 2 < G3_NCH) {
            mbar_wait(sb + 16 + b * 8, wcnt[b] & 1);
            wcnt[b]++;
            asm volatile("fence.proxy.async.shared::cta;" ::: "memory");
            gemm3_load_chunk(bufb, row0, col0, wbase, (it + 2) * 32, tid);
        }
    }
    // each buffer committed 64 times -> final completed parity = 63&1 = 1
    mbar_wait(sb + 16, 1);
    mbar_wait(sb + 24, 1);
    asm volatile("tcgen05.fence::after_thread_sync;" ::: "memory");
    __syncthreads();

    // epilogue — 128 rows x 512 cols; 8 warps: sp=row block, ch=col half (256)
    const int sp = wid & 3;
    const int ch = wid >> 2;
    float* T = (float*)(smem + (bufbase - sb)) + wid * (32 * 33);
#pragma unroll 1
    for (int cbk = 0; cbk < 8; cbk++) {
        int c0 = ch * 256 + cbk * 32;
        uint32_t r[32];
        LDTM32(r, tmem + c0);
        asm volatile("tcgen05.wait::ld.sync.aligned;" ::: "memory");
        if (z == 2) {
            // VT direct: lane = row (m), reg j = col (h*128+d)
            int m = row0 + sp * 32 + lane;
#pragma unroll
            for (int j = 0; j < 32; j++) {
                float v = __uint_as_float(r[j]);
                __nv_bfloat16 hi = __float2bfloat16_rn(v);
                __nv_bfloat16 lo = __float2bfloat16_rn(v - __bfloat162float(hi));
                int col = col0 + c0 + j;
                size_t o = ((size_t)(col >> 7) * D_DIM + (col & 127)) * L_DIM +
                           P_POS + m;
                g_VThi[o] = hi;
                g_VTlo[o] = lo;
            }
        } else {
#pragma unroll
            for (int j = 0; j < 32; j++) T[lane * 33 + j] = __uint_as_float(r[j]);
            __syncwarp();
#pragma unroll
            for (int rr = 0; rr < 32; rr++) {
                float v = T[rr * 33 + lane];
                __nv_bfloat16 hi = __float2bfloat16_rn(v);
                __nv_bfloat16 lo = __float2bfloat16_rn(v - __bfloat162float(hi));
                int row = row0 + sp * 32 + rr;
                int col = col0 + c0 + lane;
                if (z == 0) {
                    size_t o = (size_t)row * N_DIM + col;
                    g_Qhi[o] = hi;
                    g_Qlo[o] = lo;
                } else {
                    size_t o = ((size_t)(col >> 7) * L_DIM + P_POS + row) * D_DIM +
                               (col & 127);
                    g_KAhi[o] = hi;
                    g_KAlo[o] = lo;
                }
            }
            __syncwarp();
        }
    }
    __syncthreads();
    if (wid == 0) {
        asm volatile("tcgen05.dealloc.cta_group::1.sync.aligned.b32 %0, %1;"
                     :: "r"(tmem), "r"(512u));
    }
#endif
}

// ---------------------------------------------------------------------------
// Pre-pass: K cache -> g_KA [h][l][d] hi/lo (cache rows only; fresh from GEMM)
// ---------------------------------------------------------------------------
__global__ __launch_bounds__(256) void build_k_kernel(const float* __restrict__ cacheK)
{
    size_t idx = ((size_t)blockIdx.x * 256 + threadIdx.x) * 8;
    size_t rem = idx % ((size_t)L_DIM * D_DIM);
    int l = (int)(rem / D_DIM);
    if (l >= P_POS && l < P_POS + M_DIM) return;  // GEMM epilogue wrote these
    const float* src = &cacheK[idx];
    float4 f0 = *(const float4*)src;
    float4 f1 = *(const float4*)(src + 4);
    uint4 hi, lo;
    hi.x = split2(f0.x, f0.y, lo.x);
    hi.y = split2(f0.z, f0.w, lo.y);
    hi.z = split2(f1.x, f1.y, lo.z);
    hi.w = split2(f1.z, f1.w, lo.w);
    *(uint4*)&g_KAhi[idx] = hi;
    *(uint4*)&g_KAlo[idx] = lo;
}

// ---------------------------------------------------------------------------
// Pre-pass: V cache transposed -> g_VT [h][d][l] (cache rows only)
// ---------------------------------------------------------------------------
__global__ __launch_bounds__(256) void build_vt_kernel(const float* __restrict__ cacheV)
{
    const int l0 = blockIdx.x * 64;
    if (l0 >= P_POS && l0 < P_POS + M_DIM) return;  // fresh: GEMM wrote VT directly
    __shared__ __nv_bfloat16 Shi[64][65];
    __shared__ __nv_bfloat16 Slo[64][65];
    const int d0 = blockIdx.y * 64;
    const int h = blockIdx.z;
    const int tid = threadIdx.x;

#pragma unroll
    for (int j = 0; j < 16; j++) {
        int idx = tid + j * 256;
        int lr = idx >> 6, dc = idx & 63;
        float v = cacheV[((size_t)h * L_DIM + l0 + lr) * D_DIM + d0 + dc];
        __nv_bfloat16 hi = __float2bfloat16_rn(v);
        __nv_bfloat16 lo = __float2bfloat16_rn(v - __bfloat162float(hi));
        Shi[lr][dc] = hi;
        Slo[lr][dc] = lo;
    }
    __syncthreads();
#pragma unroll
    for (int j = 0; j < 16; j++) {
        int idx = tid + j * 256;
        int dr = idx >> 6, lc = idx & 63;
        size_t o = ((size_t)h * D_DIM + d0 + dr) * L_DIM + l0 + lc;
        g_VThi[o] = Shi[lc][dr];
        g_VTlo[o] = Slo[lc][dr];
    }
}

// ---------------------------------------------------------------------------
// tcgen05 attention (unchanged): BL=64, K/V/S double-buffered.
// TMEM: S0@0, S1@64, O@128, Phi@256, Plo@288.
// ---------------------------------------------------------------------------
#define A_NCH 64
#define AQ_HI 0
#define AQ_LO 32768
#define AK_BASE 65536
#define AV_BASE 131072
#define ATTN_SMEM (2112 + 1024 + 196608)
#define S_IDESC 0x8100490u
#define PV_IDESC 0x8200490u
#define TM_S 0
#define TM_O 128
#define TM_PHI 256
#define TM_PLO 288

__global__ __launch_bounds__(256) void attn_tc(float* __restrict__ out)
{
#if HAS_TC
    extern __shared__ char smem[];
    const uint32_t sb = smem_u32(smem);
    const uint32_t db = (sb + 1088 + 1023) & ~1023u;
    float* rsum_s = (float*)(smem + 64);
    const int tid = threadIdx.x;
    const int lane = tid & 31;
    const int wid = tid >> 5;
    const int sp = wid & 3;
    const int ch = wid >> 2;
    const int m0 = blockIdx.x * 128;
    const int h = blockIdx.y;

    const uint32_t mbS = sb + 16;
    const uint32_t mbP = sb + 24;

    if (wid == 0) {
        asm volatile("tcgen05.alloc.cta_group::1.sync.aligned.shared::cta.b32 [%0], %1;"
                     :: "r"(sb), "r"(512u) : "memory");
    }
    if (tid == 0) {
        mbar_init(mbS, 1);
        mbar_init(mbP, 1);
    }
    __syncthreads();
    uint32_t tmem;
    asm volatile("ld.shared.b32 %0, [%1];" : "=r"(tmem) : "r"(sb));

    const __nv_bfloat16* KAh = &g_KAhi[(size_t)h * L_DIM * D_DIM];
    const __nv_bfloat16* KAl = &g_KAlo[(size_t)h * L_DIM * D_DIM];
    const __nv_bfloat16* VTh = &g_VThi[(size_t)h * D_DIM * L_DIM];
    const __nv_bfloat16* VTl = &g_VTlo[(size_t)h * D_DIM * L_DIM];

    const uint64_t DOFF_Q[8] = {0, 2, 4, 6, 1024, 1026, 1028, 1030};
    const uint64_t DOFF_K[8] = {0, 2, 4, 6, 512, 514, 516, 518};
    const int ca3[3] = {0, 0, 1};
    const int cb3[3] = {0, 1, 0};

    ld_tile(db + AQ_HI, &g_Qhi[(size_t)m0 * N_DIM + h * D_DIM], N_DIM, tid);
    ld_tile(db + AQ_LO, &g_Qlo[(size_t)m0 * N_DIM + h * D_DIM], N_DIM, tid);
    ld_tile_k64(db + AK_BASE, &KAh[0], D_DIM, tid);
    ld_tile_k64(db + AK_BASE + 16384, &KAl[0], D_DIM, tid);
    CP_COMMIT;
    ld_tile_k64(db + AK_BASE + 32768, &KAh[(size_t)64 * D_DIM], D_DIM, tid);
    ld_tile_k64(db + AK_BASE + 49152, &KAl[(size_t)64 * D_DIM], D_DIM, tid);
    CP_COMMIT;
    ld_tile_v64(db + AV_BASE, &VTh[0], L_DIM, tid);
    ld_tile_v64(db + AV_BASE + 16384, &VTl[0], L_DIM, tid);
    CP_COMMIT;

    const uint64_t dQ0 = mk_desc(db + AQ_HI);
    const uint64_t dQ1 = mk_desc(db + AQ_LO);

    asm volatile("cp.async.wait_group 2;");
    asm volatile("fence.proxy.async.shared::cta;" ::: "memory");
    __syncthreads();
    if (wid == 0 && elect1()) {
        asm volatile("fence.proxy.async.shared::cta;" ::: "memory");
        uint64_t dQ[2] = {dQ0, dQ1};
        uint64_t dK[2] = {mk_desc(db + AK_BASE), mk_desc(db + AK_BASE + 16384)};
#pragma unroll
        for (int c = 0; c < 3; c++)
#pragma unroll
            for (int k8 = 0; k8 < 8; k8++)
                mma_ss(tmem + TM_S, dQ[ca3[c]] + DOFF_Q[k8], dK[cb3[c]] + DOFF_K[k8],
                       S_IDESC, !(c == 0 && k8 == 0));
        asm volatile(
            "tcgen05.commit.cta_group::1.mbarrier::arrive::one.shared::cluster.b64 [%0];"
            :: "r"(mbS) : "memory");
    }

    float rsum = 0.0f;

    for (int it = 0; it < A_NCH; it++) {
        mbar_wait(mbS, it & 1);
        asm volatile("tcgen05.fence::after_thread_sync;" ::: "memory");

        if (it < A_NCH - 1) {
            asm volatile("cp.async.wait_group 1;");
            asm volatile("fence.proxy.async.shared::cta;" ::: "memory");
            __syncthreads();
            if (wid == 0 && elect1()) {
                asm volatile("fence.proxy.async.shared::cta;" ::: "memory");
                const uint32_t kb = db + AK_BASE + ((it + 1) & 1) * 32768;
                uint64_t dQ[2] = {dQ0, dQ1};
                uint64_t dK[2] = {mk_desc(kb), mk_desc(kb + 16384)};
                const uint32_t sdst = tmem + TM_S + ((it + 1) & 1) * 64;
#pragma unroll
                for (int c = 0; c < 3; c++)
#pragma unroll
                    for (int k8 = 0; k8 < 8; k8++)
                        mma_ss(sdst, dQ[ca3[c]] + DOFF_Q[k8], dK[cb3[c]] + DOFF_K[k8],
                               S_IDESC, !(c == 0 && k8 == 0));
                asm volatile(
                    "tcgen05.commit.cta_group::1.mbarrier::arrive::one.shared::cluster.b64 [%0];"
                    :: "r"(mbS) : "memory");
            }
        }
        if (it + 2 < A_NCH) {
            const uint32_t kb = db + AK_BASE + (it & 1) * 32768;
            ld_tile_k64(kb, &KAh[(size_t)(it + 2) * 64 * D_DIM], D_DIM, tid);
            ld_tile_k64(kb + 16384, &KAl[(size_t)(it + 2) * 64 * D_DIM], D_DIM, tid);
            CP_COMMIT;
        }
        if (it > 0) {
            mbar_wait(mbP, (it - 1) & 1);
            asm volatile("tcgen05.fence::after_thread_sync;" ::: "memory");
        }
        if (it + 1 < A_NCH) {
            const uint32_t vb = db + AV_BASE + ((it + 1) & 1) * 32768;
            ld_tile_v64(vb, &VTh[(size_t)(it + 1) * 64], L_DIM, tid);
            ld_tile_v64(vb + 16384, &VTl[(size_t)(it + 1) * 64], L_DIM, tid);
            CP_COMMIT;
        }
        {
            const uint32_t sbuf = tmem + TM_S + (it & 1) * 64;
            uint32_t s0[32];
            LDTM32(s0, sbuf + ch * 32);
            asm volatile("tcgen05.wait::ld.sync.aligned;" ::: "memory");
            uint32_t ph[16], pl[16];
#pragma unroll
            for (int t = 0; t < 16; t++) {
                float e0 = __expf(__uint_as_float(s0[2 * t]));
                float e1 = __expf(__uint_as_float(s0[2 * t + 1]));
                rsum += e0 + e1;
                ph[t] = split2(e0, e1, pl[t]);
            }
            uint32_t wofs = ((uint32_t)sp << 21) + ch * 16;
            STTM16(tmem + TM_PHI + wofs, ph);
            STTM16(tmem + TM_PLO + wofs, pl);
            asm volatile("tcgen05.wait::st.sync.aligned;" ::: "memory");
        }
        asm volatile("tcgen05.fence::before_thread_sync;" ::: "memory");
        if (it + 2 < A_NCH)      asm volatile("cp.async.wait_group 2;");
        else if (it + 1 < A_NCH) asm volatile("cp.async.wait_group 1;");
        else                     asm volatile("cp.async.wait_group 0;");
        asm volatile("fence.proxy.async.shared::cta;" ::: "memory");
        __syncthreads();
        if (wid == 0 && elect1()) {
            asm volatile("tcgen05.fence::after_thread_sync;" ::: "memory");
            asm volatile("fence.proxy.async.shared::cta;" ::: "memory");
            const uint32_t vb = db + AV_BASE + (it & 1) * 32768;
            uint64_t dV[2] = {mk_desc(vb), mk_desc(vb + 16384)};
            const uint32_t pa[3] = {TM_PHI, TM_PHI, TM_PLO};
            const int pb[3] = {0, 1, 0};
#pragma unroll
            for (int c = 0; c < 3; c++)
#pragma unroll
                for (int k8 = 0; k8 < 4; k8++)
                    mma_ts(tmem + TM_O, tmem + pa[c] + k8 * 8, dV[pb[c]] + k8 * 2,
                           PV_IDESC, !(it == 0 && c == 0 && k8 == 0));
            asm volatile(
                "tcgen05.commit.cta_group::1.mbarrier::arrive::one.shared::cluster.b64 [%0];"
                :: "r"(mbP) : "memory");
        }
    }
    mbar_wait(mbP, (A_NCH - 1) & 1);
    asm volatile("tcgen05.fence::after_thread_sync;" ::: "memory");

    rsum_s[(sp * 32 + lane) * 2 + ch] = rsum;
    __syncthreads();

    {
        uint32_t o0[32], o1[32];
        LDTM32(o0, tmem + TM_O + ch * 64);
        LDTM32(o1, tmem + TM_O + ch * 64 + 32);
        asm volatile("tcgen05.wait::ld.sync.aligned;" ::: "memory");
        int row = sp * 32 + lane;
        float inv = 1.0f / (rsum_s[row * 2 + 0] + rsum_s[row * 2 + 1]);
        float* T = (float*)(smem + (db - sb)) + wid * (32 * 65);
#pragma unroll
        for (int j = 0; j < 32; j++) T[lane * 65 + j] = __uint_as_float(o0[j]) * inv;
#pragma unroll
        for (int j = 0; j < 32; j++) T[lane * 65 + 32 + j] = __uint_as_float(o1[j]) * inv;
        __syncwarp();
#pragma unroll
        for (int r = 0; r < 32; r++) {
            size_t o = (size_t)(m0 + sp * 32 + r) * N_DIM + h * D_DIM + ch * 64;
            out[o + lane] = T[r * 65 + lane];
            out[o + 32 + lane] = T[r * 65 + 32 + lane];
        }
    }
    __syncthreads();
    if (wid == 0) {
        asm volatile("tcgen05.dealloc.cta_group::1.sync.aligned.b32 %0, %1;"
                     :: "r"(tmem), "r"(512u));
    }
#endif
}

// ---------------------------------------------------------------------------
extern "C" void kernel_launch(void* const* d_in, const int* in_sizes, int n_in,
                              void* d_out, int out_size)
{
    const float* X = (const float*)d_in[0];
    const float* Wq = (const float*)d_in[1];
    const float* Wk = (const float*)d_in[2];
    const float* Wv = (const float*)d_in[3];
    const float* cK = (const float*)d_in[4];
    const float* cV = (const float*)d_in[5];
    float* out = (float*)d_out;

    cudaFuncSetAttribute(qkv_gemm_tc,
                         cudaFuncAttributeMaxDynamicSharedMemorySize, TC_SMEM);
    cudaFuncSetAttribute(attn_tc,
                         cudaFuncAttributeMaxDynamicSharedMemorySize, ATTN_SMEM);

    convert_x_kernel<<<2048, 256>>>(X);
    convert_w_kernel<<<dim3(64, 64, 3), 256>>>(Wq, Wk, Wv);
    qkv_gemm_tc<<<dim3(8, 8, 3), 256, TC_SMEM>>>();
    build_k_kernel<<<8192, 256>>>(cK);
    build_vt_kernel<<<dim3(64, 2, 32), 256>>>(cV);
    attn_tc<<<dim3(8, 32), 256, ATTN_SMEM>>>(out);
}

// round 13
// speedup vs baseline: 1.2783x; 1.2326x over previous
#include <cuda_runtime.h>
#include <cuda_bf16.h>
#include <math.h>
#include <stdint.h>

#define M_DIM 1024
#define N_DIM 4096
#define D_DIM 128
#define H_DIM 32
#define P_POS 2048
#define L_DIM 4096

// --- arch-specific feature gate (tcgen05 only legal in sm_103a-specific pass)
#if defined(__CUDA_ARCH__)
#if defined(__CUDA_ARCH_FEAT_SM103_ALL)
#define HAS_TC 1
#elif defined(__CUDA_ARCH_SPECIFIC__) && (__CUDA_ARCH_SPECIFIC__ == 1030)
#define HAS_TC 1
#endif
#endif
#ifndef HAS_TC
#define HAS_TC 0
#endif

// bf16-split operands.
__device__ __nv_bfloat16 g_Xhi[M_DIM * (size_t)N_DIM];
__device__ __nv_bfloat16 g_Xlo[M_DIM * (size_t)N_DIM];
__device__ __nv_bfloat16 g_Whi[3 * (size_t)N_DIM * N_DIM];
__device__ __nv_bfloat16 g_Wlo[3 * (size_t)N_DIM * N_DIM];
// GEMM outputs, bf16 hi/lo, [M][N] row-major (col = h*128+d).
__device__ __nv_bfloat16 g_Qhi[M_DIM * (size_t)N_DIM];
__device__ __nv_bfloat16 g_Qlo[M_DIM * (size_t)N_DIM];
__device__ __nv_bfloat16 g_Khi[M_DIM * (size_t)N_DIM];
__device__ __nv_bfloat16 g_Klo[M_DIM * (size_t)N_DIM];
__device__ __nv_bfloat16 g_Vhi[M_DIM * (size_t)N_DIM];
__device__ __nv_bfloat16 g_Vlo[M_DIM * (size_t)N_DIM];
// Merged cache: K_all [H][L][D], V_all transposed [H][D][L].
__device__ __nv_bfloat16 g_KAhi[(size_t)H_DIM * L_DIM * D_DIM];
__device__ __nv_bfloat16 g_KAlo[(size_t)H_DIM * L_DIM * D_DIM];
__device__ __nv_bfloat16 g_VThi[(size_t)H_DIM * D_DIM * L_DIM];
__device__ __nv_bfloat16 g_VTlo[(size_t)H_DIM * D_DIM * L_DIM];

// ---------------------------------------------------------------------------
// helpers
// ---------------------------------------------------------------------------
__device__ __forceinline__ uint32_t smem_u32(const void* p) {
    return (uint32_t)__cvta_generic_to_shared(p);
}
__device__ __forceinline__ void cp16s(uint32_t s, const void* g) {
    asm volatile("cp.async.cg.shared.global [%0], [%1], 16;" :: "r"(s), "l"(g));
}
#define CP_COMMIT asm volatile("cp.async.commit_group;")

__device__ __forceinline__ uint32_t split2(float a, float b, uint32_t& lo) {
    __nv_bfloat16 ah = __float2bfloat16_rn(a);
    __nv_bfloat16 bh = __float2bfloat16_rn(b);
    __nv_bfloat16 al = __float2bfloat16_rn(a - __bfloat162float(ah));
    __nv_bfloat16 bl = __float2bfloat16_rn(b - __bfloat162float(bh));
    lo = (uint32_t)__bfloat16_as_ushort(al) | ((uint32_t)__bfloat16_as_ushort(bl) << 16);
    return (uint32_t)__bfloat16_as_ushort(ah) | ((uint32_t)__bfloat16_as_ushort(bh) << 16);
}

#define SWZ(x) ((x) ^ ((((uint32_t)(x)) >> 3) & 0x70))

#if HAS_TC
__device__ __forceinline__ uint32_t elect1() {
    uint32_t p;
    asm volatile("{\n\t.reg .pred p;\n\telect.sync _|p, 0xFFFFFFFF;\n\t"
                 "selp.b32 %0, 1, 0, p;\n\t}" : "=r"(p));
    return p;
}
__device__ __forceinline__ void mbar_init(uint32_t m, uint32_t cnt) {
    asm volatile("mbarrier.init.shared.b64 [%0], %1;" :: "r"(m), "r"(cnt) : "memory");
}
__device__ __forceinline__ void mbar_wait(uint32_t m, uint32_t parity) {
    uint32_t done;
    asm volatile(
        "{\n\t.reg .pred p;\n\t"
        "mbarrier.try_wait.parity.acquire.cta.shared::cta.b64 p, [%1], %2;\n\t"
        "selp.b32 %0, 1, 0, p;\n\t}"
        : "=r"(done) : "r"(m), "r"(parity) : "memory");
    if (!done) {
        asm volatile(
            "{\n\t.reg .pred P1;\n\t"
            "WL_%=:\n\t"
            "mbarrier.try_wait.parity.acquire.cta.shared::cta.b64 P1, [%0], %1, 0x989680;\n\t"
            "@P1 bra.uni WD_%=;\n\t"
            "bra.uni WL_%=;\n\t"
            "WD_%=:\n\t}"
            :: "r"(m), "r"(parity) : "memory");
    }
}
__device__ __forceinline__ uint64_t mk_desc(uint32_t addr) {
    const uint64_t base = (uint64_t(2) << 61) | (uint64_t(1) << 46) |
                          (uint64_t(64) << 32) | (uint64_t(1) << 16);
    return base | ((uint64_t)(addr >> 4) & 0x3FFF);
}
__device__ __forceinline__ void mma_ss(uint32_t d, uint64_t ad, uint64_t bd,
                                       uint32_t idesc, uint32_t en) {
    asm volatile(
        "{\n\t.reg .pred p;\n\t"
        "setp.ne.u32 p, %4, 0;\n\t"
        "tcgen05.mma.cta_group::1.kind::f16 [%0], %1, %2, %3, {%5,%5,%5,%5}, p;\n\t}"
        :: "r"(d), "l"(ad), "l"(bd), "r"(idesc), "r"(en), "r"(0u) : "memory");
}
__device__ __forceinline__ void mma_ts(uint32_t d, uint32_t at, uint64_t bd,
                                       uint32_t idesc, uint32_t en) {
    asm volatile(
        "{\n\t.reg .pred p;\n\t"
        "setp.ne.u32 p, %4, 0;\n\t"
        "tcgen05.mma.cta_group::1.kind::f16 [%0], [%1], %2, %3, {%5,%5,%5,%5}, p;\n\t}"
        :: "r"(d), "r"(at), "l"(bd), "r"(idesc), "r"(en), "r"(0u) : "memory");
}
#define LDTM32(r, a)                                                            \
    asm volatile(                                                               \
        "tcgen05.ld.sync.aligned.32x32b.x32.b32 "                               \
        "{%0,%1,%2,%3,%4,%5,%6,%7,%8,%9,%10,%11,%12,%13,%14,%15,"               \
        "%16,%17,%18,%19,%20,%21,%22,%23,%24,%25,%26,%27,%28,%29,%30,%31},[%32];" \
        : "=r"((r)[0]), "=r"((r)[1]), "=r"((r)[2]), "=r"((r)[3]),               \
          "=r"((r)[4]), "=r"((r)[5]), "=r"((r)[6]), "=r"((r)[7]),               \
          "=r"((r)[8]), "=r"((r)[9]), "=r"((r)[10]), "=r"((r)[11]),             \
          "=r"((r)[12]), "=r"((r)[13]), "=r"((r)[14]), "=r"((r)[15]),           \
          "=r"((r)[16]), "=r"((r)[17]), "=r"((r)[18]), "=r"((r)[19]),           \
          "=r"((r)[20]), "=r"((r)[21]), "=r"((r)[22]), "=r"((r)[23]),           \
          "=r"((r)[24]), "=r"((r)[25]), "=r"((r)[26]), "=r"((r)[27]),           \
          "=r"((r)[28]), "=r"((r)[29]), "=r"((r)[30]), "=r"((r)[31])            \
        : "r"(a))
#define STTM16(a, r)                                                            \
    asm volatile(                                                               \
        "tcgen05.st.sync.aligned.32x32b.x16.b32 [%0], "                         \
        "{%1,%2,%3,%4,%5,%6,%7,%8,%9,%10,%11,%12,%13,%14,%15,%16};"             \
        :: "r"(a),                                                              \
           "r"((r)[0]), "r"((r)[1]), "r"((r)[2]), "r"((r)[3]),                  \
           "r"((r)[4]), "r"((r)[5]), "r"((r)[6]), "r"((r)[7]),                  \
           "r"((r)[8]), "r"((r)[9]), "r"((r)[10]), "r"((r)[11]),                \
           "r"((r)[12]), "r"((r)[13]), "r"((r)[14]), "r"((r)[15])               \
        : "memory")

// 128x128 bf16 tile (atom-blocked K-major SW128, 256B logical rows)
__device__ __forceinline__ void ld_tile(uint32_t sdst, const __nv_bfloat16* g,
                                        size_t stride, int tid) {
#pragma unroll
    for (int j = 0; j < 8; j++) {
        int u = tid + j * 256;
        int r = u >> 4;
        int c8 = u & 15;
        uint32_t so = (uint32_t)(((r >> 3) + (c8 >> 3) * 16) * 1024 +
                                 (r & 7) * 128 + (c8 & 7) * 16);
        cp16s(sdst + SWZ(so), g + (size_t)r * stride + c8 * 8);
    }
}
// 64x128 bf16 tile (atom-blocked, 8 atoms per 128B-col-block)
__device__ __forceinline__ void ld_tile_k64(uint32_t sdst, const __nv_bfloat16* g,
                                            size_t stride, int tid) {
#pragma unroll
    for (int j = 0; j < 4; j++) {
        int u = tid + j * 256;
        int r = u >> 4;
        int c8 = u & 15;
        uint32_t so = (uint32_t)(((r >> 3) + (c8 >> 3) * 8) * 1024 +
                                 (r & 7) * 128 + (c8 & 7) * 16);
        cp16s(sdst + SWZ(so), g + (size_t)r * stride + c8 * 8);
    }
}
// 128x64 bf16 tile (128B rows, single atom column)
__device__ __forceinline__ void ld_tile_v64(uint32_t sdst, const __nv_bfloat16* g,
                                            size_t stride, int tid) {
#pragma unroll
    for (int j = 0; j < 4; j++) {
        int u = tid + j * 256;
        int r = u >> 3;
        int c8 = u & 7;
        uint32_t so = (uint32_t)((r >> 3) * 1024 + (r & 7) * 128 + c8 * 16);
        cp16s(sdst + SWZ(so), g + (size_t)r * stride + c8 * 8);
    }
}
#endif  // HAS_TC

// ---------------------------------------------------------------------------
// Pre-pass: X fp32 -> bf16 hi/lo
// ---------------------------------------------------------------------------
__global__ __launch_bounds__(256) void convert_x_kernel(const float* __restrict__ X) {
    size_t i0 = ((size_t)blockIdx.x * 256 + threadIdx.x) * 8;
    float4 f0 = *(const float4*)&X[i0];
    float4 f1 = *(const float4*)&X[i0 + 4];
    uint4 hi, lo;
    hi.x = split2(f0.x, f0.y, lo.x);
    hi.y = split2(f0.z, f0.w, lo.y);
    hi.z = split2(f1.x, f1.y, lo.z);
    hi.w = split2(f1.z, f1.w, lo.w);
    *(uint4*)&g_Xhi[i0] = hi;
    *(uint4*)&g_Xlo[i0] = lo;
}

// ---------------------------------------------------------------------------
// Pre-pass: W [k][n] fp32 -> WT [n][k] bf16 hi/lo
// ---------------------------------------------------------------------------
__global__ __launch_bounds__(256) void convert_w_kernel(
    const float* __restrict__ Wq, const float* __restrict__ Wk,
    const float* __restrict__ Wv)
{
    __shared__ float sm[64][65];
    const float* W = (blockIdx.z == 0) ? Wq : (blockIdx.z == 1) ? Wk : Wv;
    const size_t wo = (size_t)blockIdx.z * N_DIM * N_DIM;
    const int k0 = blockIdx.x * 64;
    const int n0 = blockIdx.y * 64;
    const int tid = threadIdx.x;

#pragma unroll
    for (int j = 0; j < 16; j++) {
        int idx = tid + j * 256;
        int kr = idx >> 6, nc = idx & 63;
        sm[kr][nc] = W[(size_t)(k0 + kr) * N_DIM + n0 + nc];
    }
    __syncthreads();
#pragma unroll
    for (int j = 0; j < 8; j++) {
        int idx = tid + j * 256;
        int ni = idx >> 5, kp = idx & 31;
        float a = sm[kp * 2][ni];
        float b = sm[kp * 2 + 1][ni];
        uint32_t lo, hi = split2(a, b, lo);
        size_t o = wo + (size_t)(n0 + ni) * N_DIM + k0 + kp * 2;
        *(uint32_t*)&g_Whi[o] = hi;
        *(uint32_t*)&g_Wlo[o] = lo;
    }
}

// ---------------------------------------------------------------------------
// tcgen05 bf16x3-split GEMM (R7 config), pipelined double buffer.
// Epilogue: z=0 -> g_Q, z=1 -> g_K (row-major, as R7); z=2 -> g_VT DIRECT.
// ---------------------------------------------------------------------------
#define G_ABUF 16384
#define G_BBUF 32768
#define G_BUFSZ (2 * G_ABUF + 2 * G_BBUF)
#define TC_SMEM (2048 + 2 * G_BUFSZ)
#define G_IDESC 0x8400490u
#define G_NCH 64

#if HAS_TC
__device__ __forceinline__ void gemm_load_chunk(uint32_t bufb, int row0, int col0,
                                                size_t wbase, int k0, int tid) {
#pragma unroll
    for (int j = 0; j < 4; j++) {
        int u = tid + j * 256;
        int r = u >> 3, c8 = u & 7;
        size_t gsrc = (size_t)(row0 + r) * N_DIM + k0 + c8 * 8;
        uint32_t so = SWZ((uint32_t)(r * 128 + c8 * 16));
        cp16s(bufb + so, &g_Xhi[gsrc]);
        cp16s(bufb + G_ABUF + so, &g_Xlo[gsrc]);
    }
#pragma unroll
    for (int j = 0; j < 8; j++) {
        int u = tid + j * 256;
        int r = u >> 3, c8 = u & 7;
        size_t gsrc = wbase + (size_t)(col0 + r) * N_DIM + k0 + c8 * 8;
        uint32_t so = SWZ((uint32_t)(r * 128 + c8 * 16));
        cp16s(bufb + 2 * G_ABUF + so, &g_Whi[gsrc]);
        cp16s(bufb + 2 * G_ABUF + G_BBUF + so, &g_Wlo[gsrc]);
    }
    CP_COMMIT;
}
#endif

__global__ __launch_bounds__(256) void qkv_gemm_tc()
{
#if HAS_TC
    extern __shared__ char smem[];
    const uint32_t sb = smem_u32(smem);
    const uint32_t bufbase = (sb + 1024 + 1023) & ~1023u;
    const int tid = threadIdx.x;
    const int lane = tid & 31;
    const int wid = tid >> 5;
    const int row0 = blockIdx.y * 128;
    const int col0 = blockIdx.x * 256;
    const int z = blockIdx.z;
    const size_t wbase = (size_t)z * N_DIM * N_DIM;
    __nv_bfloat16* Chi = (z == 0) ? g_Qhi : g_Khi;
    __nv_bfloat16* Clo = (z == 0) ? g_Qlo : g_Klo;

    if (wid == 0) {
        asm volatile("tcgen05.alloc.cta_group::1.sync.aligned.shared::cta.b32 [%0], %1;"
                     :: "r"(sb), "r"(256u) : "memory");
    }
    if (tid == 0) {
        mbar_init(sb + 16, 1);
        mbar_init(sb + 24, 1);
    }
    __syncthreads();
    uint32_t tmem;
    asm volatile("ld.shared.b32 %0, [%1];" : "=r"(tmem) : "r"(sb));

    gemm_load_chunk(bufbase, row0, col0, wbase, 0, tid);
    gemm_load_chunk(bufbase + G_BUFSZ, row0, col0, wbase, 64, tid);

    int wcnt[2] = {0, 0};
    for (int it = 0; it < G_NCH; it++) {
        const int b = it & 1;
        const uint32_t bufb = bufbase + b * G_BUFSZ;
        asm volatile("cp.async.wait_group 1;");
        asm volatile("fence.proxy.async.shared::cta;" ::: "memory");
        __syncthreads();

        if (wid == 0 && elect1()) {
            asm volatile("fence.proxy.async.shared::cta;" ::: "memory");
            uint64_t dA[2] = {mk_desc(bufb), mk_desc(bufb + G_ABUF)};
            uint64_t dB[2] = {mk_desc(bufb + 2 * G_ABUF),
                              mk_desc(bufb + 2 * G_ABUF + G_BBUF)};
            const int ca[3] = {0, 0, 1};
            const int cb[3] = {0, 1, 0};
#pragma unroll
            for (int c = 0; c < 3; c++)
#pragma unroll
                for (int k8 = 0; k8 < 4; k8++) {
                    uint32_t en = !(it == 0 && c == 0 && k8 == 0);
                    mma_ss(tmem, dA[ca[c]] + k8 * 2, dB[cb[c]] + k8 * 2, G_IDESC, en);
                }
            asm volatile(
                "tcgen05.commit.cta_group::1.mbarrier::arrive::one.shared::cluster.b64 [%0];"
                :: "r"(sb + 16 + b * 8) : "memory");
        }

        if (it + 2 < G_NCH) {
            mbar_wait(sb + 16 + b * 8, wcnt[b] & 1);
            wcnt[b]++;
            asm volatile("fence.proxy.async.shared::cta;" ::: "memory");
            gemm_load_chunk(bufb, row0, col0, wbase, (it + 2) * 64, tid);
        }
    }
    mbar_wait(sb + 16, 1);
    mbar_wait(sb + 24, 1);
    asm volatile("tcgen05.fence::after_thread_sync;" ::: "memory");
    __syncthreads();

    // epilogue: LDTM -> split -> (z<2: smem transpose row-major; z==2: VT direct)
    const int sp = wid & 3;
    const int ch = wid >> 2;
    float* T = (float*)(smem + (bufbase - sb)) + wid * (32 * 33);
#pragma unroll 1
    for (int cbk = 0; cbk < 4; cbk++) {
        int c0 = ch * 128 + cbk * 32;
        uint32_t r[32];
        LDTM32(r, tmem + c0);
        asm volatile("tcgen05.wait::ld.sync.aligned;" ::: "memory");
        if (z == 2) {
            // lane = row (m), reg j = col (h*128+d); l-contiguous across lanes
            int m = row0 + sp * 32 + lane;
#pragma unroll
            for (int j = 0; j < 32; j++) {
                float v = __uint_as_float(r[j]);
                __nv_bfloat16 hi = __float2bfloat16_rn(v);
                __nv_bfloat16 lo = __float2bfloat16_rn(v - __bfloat162float(hi));
                int col = col0 + c0 + j;
                size_t o = ((size_t)(col >> 7) * D_DIM + (col & 127)) * L_DIM +
                           P_POS + m;
                g_VThi[o] = hi;
                g_VTlo[o] = lo;
            }
        } else {
#pragma unroll
            for (int j = 0; j < 32; j++) T[lane * 33 + j] = __uint_as_float(r[j]);
            __syncwarp();
#pragma unroll
            for (int rr = 0; rr < 32; rr++) {
                float v = T[rr * 33 + lane];
                __nv_bfloat16 hi = __float2bfloat16_rn(v);
                __nv_bfloat16 lo = __float2bfloat16_rn(v - __bfloat162float(hi));
                size_t o = (size_t)(row0 + sp * 32 + rr) * N_DIM + col0 + c0 + lane;
                Chi[o] = hi;
                Clo[o] = lo;
            }
            __syncwarp();
        }
    }
    __syncthreads();
    if (wid == 0) {
        asm volatile("tcgen05.dealloc.cta_group::1.sync.aligned.b32 %0, %1;"
                     :: "r"(tmem), "r"(256u));
    }
#endif
}

// ---------------------------------------------------------------------------
// Pre-pass: merged K cache -> g_KA [h][l][d] hi/lo (R7: fresh from g_K)
// ---------------------------------------------------------------------------
__global__ __launch_bounds__(256) void build_k_kernel(const float* __restrict__ cacheK)
{
    size_t idx = ((size_t)blockIdx.x * 256 + threadIdx.x) * 8;
    int h = (int)(idx / ((size_t)L_DIM * D_DIM));
    size_t rem = idx - (size_t)h * L_DIM * D_DIM;
    int l = (int)(rem / D_DIM);
    int d = (int)(rem % D_DIM);
    if (l >= P_POS && l < P_POS + M_DIM) {
        size_t s = (size_t)(l - P_POS) * N_DIM + h * D_DIM + d;
        *(uint4*)&g_KAhi[idx] = *(const uint4*)&g_Khi[s];
        *(uint4*)&g_KAlo[idx] = *(const uint4*)&g_Klo[s];
    } else {
        const float* src = &cacheK[idx];
        float4 f0 = *(const float4*)src;
        float4 f1 = *(const float4*)(src + 4);
        uint4 hi, lo;
        hi.x = split2(f0.x, f0.y, lo.x);
        hi.y = split2(f0.z, f0.w, lo.y);
        hi.z = split2(f1.x, f1.y, lo.z);
        hi.w = split2(f1.z, f1.w, lo.w);
        *(uint4*)&g_KAhi[idx] = hi;
        *(uint4*)&g_KAlo[idx] = lo;
    }
}

// ---------------------------------------------------------------------------
// Pre-pass: V cache transposed -> g_VT [h][d][l] (cache rows only; fresh
// rows written directly by the GEMM z==2 epilogue)
// ---------------------------------------------------------------------------
__global__ __launch_bounds__(256) void build_vt_kernel(const float* __restrict__ cacheV)
{
    const int l0 = blockIdx.x * 64;
    if (l0 >= P_POS && l0 < P_POS + M_DIM) return;  // fresh: GEMM wrote VT directly
    __shared__ __nv_bfloat16 Shi[64][65];
    __shared__ __nv_bfloat16 Slo[64][65];
    const int d0 = blockIdx.y * 64;
    const int h = blockIdx.z;
    const int tid = threadIdx.x;

#pragma unroll
    for (int j = 0; j < 16; j++) {
        int idx = tid + j * 256;
        int lr = idx >> 6, dc = idx & 63;
        float v = cacheV[((size_t)h * L_DIM + l0 + lr) * D_DIM + d0 + dc];
        __nv_bfloat16 hi = __float2bfloat16_rn(v);
        __nv_bfloat16 lo = __float2bfloat16_rn(v - __bfloat162float(hi));
        Shi[lr][dc] = hi;
        Slo[lr][dc] = lo;
    }
    __syncthreads();
#pragma unroll
    for (int j = 0; j < 16; j++) {
        int idx = tid + j * 256;
        int dr = idx >> 6, lc = idx & 63;
        size_t o = ((size_t)h * D_DIM + d0 + dr) * L_DIM + l0 + lc;
        g_VThi[o] = Shi[lc][dr];
        g_VTlo[o] = Slo[lc][dr];
    }
}

// ---------------------------------------------------------------------------
// tcgen05 attention (R7, unchanged): BL=64, K/V/S double-buffered, early S.
// TMEM: S0@0, S1@64, O@128, Phi@256, Plo@288.
// ---------------------------------------------------------------------------
#define A_NCH 64
#define AQ_HI 0
#define AQ_LO 32768
#define AK_BASE 65536
#define AV_BASE 131072
#define ATTN_SMEM (2112 + 1024 + 196608)
#define S_IDESC 0x8100490u
#define PV_IDESC 0x8200490u
#define TM_S 0
#define TM_O 128
#define TM_PHI 256
#define TM_PLO 288

__global__ __launch_bounds__(256) void attn_tc(float* __restrict__ out)
{
#if HAS_TC
    extern __shared__ char smem[];
    const uint32_t sb = smem_u32(smem);
    const uint32_t db = (sb + 1088 + 1023) & ~1023u;
    float* rsum_s = (float*)(smem + 64);
    const int tid = threadIdx.x;
    const int lane = tid & 31;
    const int wid = tid >> 5;
    const int sp = wid & 3;
    const int ch = wid >> 2;
    const int m0 = blockIdx.x * 128;
    const int h = blockIdx.y;

    const uint32_t mbS = sb + 16;
    const uint32_t mbP = sb + 24;

    if (wid == 0) {
        asm volatile("tcgen05.alloc.cta_group::1.sync.aligned.shared::cta.b32 [%0], %1;"
                     :: "r"(sb), "r"(512u) : "memory");
    }
    if (tid == 0) {
        mbar_init(mbS, 1);
        mbar_init(mbP, 1);
    }
    __syncthreads();
    uint32_t tmem;
    asm volatile("ld.shared.b32 %0, [%1];" : "=r"(tmem) : "r"(sb));

    const __nv_bfloat16* KAh = &g_KAhi[(size_t)h * L_DIM * D_DIM];
    const __nv_bfloat16* KAl = &g_KAlo[(size_t)h * L_DIM * D_DIM];
    const __nv_bfloat16* VTh = &g_VThi[(size_t)h * D_DIM * L_DIM];
    const __nv_bfloat16* VTl = &g_VTlo[(size_t)h * D_DIM * L_DIM];

    const uint64_t DOFF_Q[8] = {0, 2, 4, 6, 1024, 1026, 1028, 1030};
    const uint64_t DOFF_K[8] = {0, 2, 4, 6, 512, 514, 516, 518};
    const int ca3[3] = {0, 0, 1};
    const int cb3[3] = {0, 1, 0};

    ld_tile(db + AQ_HI, &g_Qhi[(size_t)m0 * N_DIM + h * D_DIM], N_DIM, tid);
    ld_tile(db + AQ_LO, &g_Qlo[(size_t)m0 * N_DIM + h * D_DIM], N_DIM, tid);
    ld_tile_k64(db + AK_BASE, &KAh[0], D_DIM, tid);
    ld_tile_k64(db + AK_BASE + 16384, &KAl[0], D_DIM, tid);
    CP_COMMIT;
    ld_tile_k64(db + AK_BASE + 32768, &KAh[(size_t)64 * D_DIM], D_DIM, tid);
    ld_tile_k64(db + AK_BASE + 49152, &KAl[(size_t)64 * D_DIM], D_DIM, tid);
    CP_COMMIT;
    ld_tile_v64(db + AV_BASE, &VTh[0], L_DIM, tid);
    ld_tile_v64(db + AV_BASE + 16384, &VTl[0], L_DIM, tid);
    CP_COMMIT;

    const uint64_t dQ0 = mk_desc(db + AQ_HI);
    const uint64_t dQ1 = mk_desc(db + AQ_LO);

    asm volatile("cp.async.wait_group 2;");
    asm volatile("fence.proxy.async.shared::cta;" ::: "memory");
    __syncthreads();
    if (wid == 0 && elect1()) {
        asm volatile("fence.proxy.async.shared::cta;" ::: "memory");
        uint64_t dQ[2] = {dQ0, dQ1};
        uint64_t dK[2] = {mk_desc(db + AK_BASE), mk_desc(db + AK_BASE + 16384)};
#pragma unroll
        for (int c = 0; c < 3; c++)
#pragma unroll
            for (int k8 = 0; k8 < 8; k8++)
                mma_ss(tmem + TM_S, dQ[ca3[c]] + DOFF_Q[k8], dK[cb3[c]] + DOFF_K[k8],
                       S_IDESC, !(c == 0 && k8 == 0));
        asm volatile(
            "tcgen05.commit.cta_group::1.mbarrier::arrive::one.shared::cluster.b64 [%0];"
            :: "r"(mbS) : "memory");
    }

    float rsum = 0.0f;

    for (int it = 0; it < A_NCH; it++) {
        mbar_wait(mbS, it & 1);
        asm volatile("tcgen05.fence::after_thread_sync;" ::: "memory");

        if (it < A_NCH - 1) {
            asm volatile("cp.async.wait_group 1;");
            asm volatile("fence.proxy.async.shared::cta;" ::: "memory");
            __syncthreads();
            if (wid == 0 && elect1()) {
                asm volatile("fence.proxy.async.shared::cta;" ::: "memory");
                const uint32_t kb = db + AK_BASE + ((it + 1) & 1) * 32768;
                uint64_t dQ[2] = {dQ0, dQ1};
                uint64_t dK[2] = {mk_desc(kb), mk_desc(kb + 16384)};
                const uint32_t sdst = tmem + TM_S + ((it + 1) & 1) * 64;
#pragma unroll
                for (int c = 0; c < 3; c++)
#pragma unroll
                    for (int k8 = 0; k8 < 8; k8++)
                        mma_ss(sdst, dQ[ca3[c]] + DOFF_Q[k8], dK[cb3[c]] + DOFF_K[k8],
                               S_IDESC, !(c == 0 && k8 == 0));
                asm volatile(
                    "tcgen05.commit.cta_group::1.mbarrier::arrive::one.shared::cluster.b64 [%0];"
                    :: "r"(mbS) : "memory");
            }
        }
        if (it + 2 < A_NCH) {
            const uint32_t kb = db + AK_BASE + (it & 1) * 32768;
            ld_tile_k64(kb, &KAh[(size_t)(it + 2) * 64 * D_DIM], D_DIM, tid);
            ld_tile_k64(kb + 16384, &KAl[(size_t)(it + 2) * 64 * D_DIM], D_DIM, tid);
            CP_COMMIT;
        }
        if (it > 0) {
            mbar_wait(mbP, (it - 1) & 1);
            asm volatile("tcgen05.fence::after_thread_sync;" ::: "memory");
        }
        if (it + 1 < A_NCH) {
            const uint32_t vb = db + AV_BASE + ((it + 1) & 1) * 32768;
            ld_tile_v64(vb, &VTh[(size_t)(it + 1) * 64], L_DIM, tid);
            ld_tile_v64(vb + 16384, &VTl[(size_t)(it + 1) * 64], L_DIM, tid);
            CP_COMMIT;
        }
        {
            const uint32_t sbuf = tmem + TM_S + (it & 1) * 64;
            uint32_t s0[32];
            LDTM32(s0, sbuf + ch * 32);
            asm volatile("tcgen05.wait::ld.sync.aligned;" ::: "memory");
            uint32_t ph[16], pl[16];
#pragma unroll
            for (int t = 0; t < 16; t++) {
                float e0 = __expf(__uint_as_float(s0[2 * t]));
                float e1 = __expf(__uint_as_float(s0[2 * t + 1]));
                rsum += e0 + e1;
                ph[t] = split2(e0, e1, pl[t]);
            }
            uint32_t wofs = ((uint32_t)sp << 21) + ch * 16;
            STTM16(tmem + TM_PHI + wofs, ph);
            STTM16(tmem + TM_PLO + wofs, pl);
            asm volatile("tcgen05.wait::st.sync.aligned;" ::: "memory");
        }
        asm volatile("tcgen05.fence::before_thread_sync;" ::: "memory");
        if (it + 2 < A_NCH)      asm volatile("cp.async.wait_group 2;");
        else if (it + 1 < A_NCH) asm volatile("cp.async.wait_group 1;");
        else                     asm volatile("cp.async.wait_group 0;");
        asm volatile("fence.proxy.async.shared::cta;" ::: "memory");
        __syncthreads();
        if (wid == 0 && elect1()) {
            asm volatile("tcgen05.fence::after_thread_sync;" ::: "memory");
            asm volatile("fence.proxy.async.shared::cta;" ::: "memory");
            const uint32_t vb = db + AV_BASE + (it & 1) * 32768;
            uint64_t dV[2] = {mk_desc(vb), mk_desc(vb + 16384)};
            const uint32_t pa[3] = {TM_PHI, TM_PHI, TM_PLO};
            const int pb[3] = {0, 1, 0};
#pragma unroll
            for (int c = 0; c < 3; c++)
#pragma unroll
                for (int k8 = 0; k8 < 4; k8++)
                    mma_ts(tmem + TM_O, tmem + pa[c] + k8 * 8, dV[pb[c]] + k8 * 2,
                           PV_IDESC, !(it == 0 && c == 0 && k8 == 0));
            asm volatile(
                "tcgen05.commit.cta_group::1.mbarrier::arrive::one.shared::cluster.b64 [%0];"
                :: "r"(mbP) : "memory");
        }
    }
    mbar_wait(mbP, (A_NCH - 1) & 1);
    asm volatile("tcgen05.fence::after_thread_sync;" ::: "memory");

    rsum_s[(sp * 32 + lane) * 2 + ch] = rsum;
    __syncthreads();

    {
        uint32_t o0[32], o1[32];
        LDTM32(o0, tmem + TM_O + ch * 64);
        LDTM32(o1, tmem + TM_O + ch * 64 + 32);
        asm volatile("tcgen05.wait::ld.sync.aligned;" ::: "memory");
        int row = sp * 32 + lane;
        float inv = 1.0f / (rsum_s[row * 2 + 0] + rsum_s[row * 2 + 1]);
        float* T = (float*)(smem + (db - sb)) + wid * (32 * 65);
#pragma unroll
        for (int j = 0; j < 32; j++) T[lane * 65 + j] = __uint_as_float(o0[j]) * inv;
#pragma unroll
        for (int j = 0; j < 32; j++) T[lane * 65 + 32 + j] = __uint_as_float(o1[j]) * inv;
        __syncwarp();
#pragma unroll
        for (int r = 0; r < 32; r++) {
            size_t o = (size_t)(m0 + sp * 32 + r) * N_DIM + h * D_DIM + ch * 64;
            out[o + lane] = T[r * 65 + lane];
            out[o + 32 + lane] = T[r * 65 + 32 + lane];
        }
    }
    __syncthreads();
    if (wid == 0) {
        asm volatile("tcgen05.dealloc.cta_group::1.sync.aligned.b32 %0, %1;"
                     :: "r"(tmem), "r"(512u));
    }
#endif
}

// ---------------------------------------------------------------------------
extern "C" void kernel_launch(void* const* d_in, const int* in_sizes, int n_in,
                              void* d_out, int out_size)
{
    const float* X = (const float*)d_in[0];
    const float* Wq = (const float*)d_in[1];
    const float* Wk = (const float*)d_in[2];
    const float* Wv = (const float*)d_in[3];
    const float* cK = (const float*)d_in[4];
    const float* cV = (const float*)d_in[5];
    float* out = (float*)d_out;

    cudaFuncSetAttribute(qkv_gemm_tc,
                         cudaFuncAttributeMaxDynamicSharedMemorySize, TC_SMEM);
    cudaFuncSetAttribute(attn_tc,
                         cudaFuncAttributeMaxDynamicSharedMemorySize, ATTN_SMEM);

    convert_x_kernel<<<2048, 256>>>(X);
    convert_w_kernel<<<dim3(64, 64, 3), 256>>>(Wq, Wk, Wv);
    qkv_gemm_tc<<<dim3(16, 8, 3), 256, TC_SMEM>>>();
    build_k_kernel<<<8192, 256>>>(cK);
    build_vt_kernel<<<dim3(64, 2, 32), 256>>>(cV);
    attn_tc<<<dim3(8, 32), 256, ATTN_SMEM>>>(out);
}